// round 2
// baseline (speedup 1.0000x reference)
#include <cuda_runtime.h>
#include <math.h>

#define SEQ 4096
#define FEAT 1024
#define HID 1024
#define NH 8
#define DK 128

// Scratch (device globals: allocation-free per harness rules)
__device__ float g_Q[(size_t)SEQ * HID];
__device__ float g_K[(size_t)SEQ * HID];
__device__ float g_V[(size_t)SEQ * HID];
__device__ float g_Y[(size_t)SEQ * HID];
// Fallback attn buffer in case harness out only holds y (536 MB, bss-style)
__device__ float g_attn_fb[(size_t)NH * SEQ * SEQ];

// ---------------------------------------------------------------------------
// Classic 128x128x8 double-buffered SGEMM, 256 threads, 8x8 per thread.
// BT=false: C[M,N] = alpha * A[M,K] @ B[K,N]
// BT=true : C[M,N] = alpha * A[M,K] @ B[N,K]^T   (both operands K-major)
// Per-z strides (sA,sB,sC) give batched-head behavior via blockIdx.z.
// All dims here are multiples of the tile sizes; no edge handling needed.
// ---------------------------------------------------------------------------
template <bool BT>
__launch_bounds__(256, 2)
__global__ void sgemm128(const float* __restrict__ A, const float* __restrict__ B,
                         float* __restrict__ C, int M, int N, int K,
                         int lda, int ldb, int ldc, float alpha,
                         size_t sA, size_t sB, size_t sC)
{
    constexpr int BM = 128, BN = 128, BK = 8;
    __shared__ float As[2][BK][BM];
    __shared__ float Bs[2][BK][BN];

    A += (size_t)blockIdx.z * sA;
    B += (size_t)blockIdx.z * sB;
    C += (size_t)blockIdx.z * sC;

    const int bm = blockIdx.y * BM;
    const int bn = blockIdx.x * BN;
    const int tid = threadIdx.x;
    const int tx = tid & 15;       // 0..15 -> output cols tx*8
    const int ty = tid >> 4;       // 0..15 -> output rows ty*8

    // A-tile loader: 128 rows x 8 k, each thread one float4 along K
    const int arow = tid >> 1;
    const int akk  = (tid & 1) * 4;
    // B-tile loader
    const int brow = BT ? (tid >> 1) : (tid >> 5);
    const int bkk  = BT ? (tid & 1) * 4 : 0;
    const int bcol = BT ? 0 : (tid & 31) * 4;

    float acc[8][8];
#pragma unroll
    for (int i = 0; i < 8; i++)
#pragma unroll
        for (int j = 0; j < 8; j++) acc[i][j] = 0.0f;

    const int ntiles = K / BK;

    // Prologue: tile 0
    float4 a4 = *reinterpret_cast<const float4*>(A + (size_t)(bm + arow) * lda + akk);
    float4 b4;
    if (BT) b4 = *reinterpret_cast<const float4*>(B + (size_t)(bn + brow) * ldb + bkk);
    else    b4 = *reinterpret_cast<const float4*>(B + (size_t)brow * ldb + bn + bcol);

    As[0][akk + 0][arow] = a4.x;
    As[0][akk + 1][arow] = a4.y;
    As[0][akk + 2][arow] = a4.z;
    As[0][akk + 3][arow] = a4.w;
    if (BT) {
        Bs[0][bkk + 0][brow] = b4.x;
        Bs[0][bkk + 1][brow] = b4.y;
        Bs[0][bkk + 2][brow] = b4.z;
        Bs[0][bkk + 3][brow] = b4.w;
    } else {
        *reinterpret_cast<float4*>(&Bs[0][brow][bcol]) = b4;
    }
    __syncthreads();

    for (int t = 0; t < ntiles; t++) {
        const int cur = t & 1;
        if (t + 1 < ntiles) {
            const int k0 = (t + 1) * BK;
            a4 = *reinterpret_cast<const float4*>(A + (size_t)(bm + arow) * lda + k0 + akk);
            if (BT) b4 = *reinterpret_cast<const float4*>(B + (size_t)(bn + brow) * ldb + k0 + bkk);
            else    b4 = *reinterpret_cast<const float4*>(B + (size_t)(k0 + brow) * ldb + bn + bcol);
        }
#pragma unroll
        for (int k = 0; k < BK; k++) {
            float ar[8], br[8];
            *reinterpret_cast<float4*>(ar)     = *reinterpret_cast<float4*>(&As[cur][k][ty * 8]);
            *reinterpret_cast<float4*>(ar + 4) = *reinterpret_cast<float4*>(&As[cur][k][ty * 8 + 4]);
            *reinterpret_cast<float4*>(br)     = *reinterpret_cast<float4*>(&Bs[cur][k][tx * 8]);
            *reinterpret_cast<float4*>(br + 4) = *reinterpret_cast<float4*>(&Bs[cur][k][tx * 8 + 4]);
#pragma unroll
            for (int i = 0; i < 8; i++)
#pragma unroll
                for (int j = 0; j < 8; j++)
                    acc[i][j] += ar[i] * br[j];
        }
        if (t + 1 < ntiles) {
            const int nxt = cur ^ 1;
            As[nxt][akk + 0][arow] = a4.x;
            As[nxt][akk + 1][arow] = a4.y;
            As[nxt][akk + 2][arow] = a4.z;
            As[nxt][akk + 3][arow] = a4.w;
            if (BT) {
                Bs[nxt][bkk + 0][brow] = b4.x;
                Bs[nxt][bkk + 1][brow] = b4.y;
                Bs[nxt][bkk + 2][brow] = b4.z;
                Bs[nxt][bkk + 3][brow] = b4.w;
            } else {
                *reinterpret_cast<float4*>(&Bs[nxt][brow][bcol]) = b4;
            }
            __syncthreads();
        }
    }

    // Epilogue
#pragma unroll
    for (int i = 0; i < 8; i++) {
        float* cp = C + (size_t)(bm + ty * 8 + i) * ldc + bn + tx * 8;
        float4 o0, o1;
        o0.x = acc[i][0] * alpha; o0.y = acc[i][1] * alpha;
        o0.z = acc[i][2] * alpha; o0.w = acc[i][3] * alpha;
        o1.x = acc[i][4] * alpha; o1.y = acc[i][5] * alpha;
        o1.z = acc[i][6] * alpha; o1.w = acc[i][7] * alpha;
        *reinterpret_cast<float4*>(cp)     = o0;
        *reinterpret_cast<float4*>(cp + 4) = o1;
    }
}

// ---------------------------------------------------------------------------
// Row softmax, in place. One block (256 threads) per row of 4096 floats.
// gridDim.x = NH*SEQ.
// ---------------------------------------------------------------------------
__global__ void softmax_rows(float* __restrict__ attn)
{
    __shared__ float sred[8];
    const size_t row = blockIdx.x;
    float4* p = reinterpret_cast<float4*>(attn + row * (size_t)SEQ);
    const int tid = threadIdx.x;
    const int lane = tid & 31, wid = tid >> 5;

    float4 v[4];
    float m = -1e30f;
#pragma unroll
    for (int i = 0; i < 4; i++) {
        v[i] = p[tid + i * 256];
        m = fmaxf(m, fmaxf(fmaxf(v[i].x, v[i].y), fmaxf(v[i].z, v[i].w)));
    }
#pragma unroll
    for (int o = 16; o; o >>= 1) m = fmaxf(m, __shfl_xor_sync(0xffffffffu, m, o));
    if (lane == 0) sred[wid] = m;
    __syncthreads();
    m = sred[0];
#pragma unroll
    for (int i = 1; i < 8; i++) m = fmaxf(m, sred[i]);

    float s = 0.0f;
#pragma unroll
    for (int i = 0; i < 4; i++) {
        v[i].x = __expf(v[i].x - m);
        v[i].y = __expf(v[i].y - m);
        v[i].z = __expf(v[i].z - m);
        v[i].w = __expf(v[i].w - m);
        s += v[i].x + v[i].y + v[i].z + v[i].w;
    }
    __syncthreads();   // protect sred reuse
#pragma unroll
    for (int o = 16; o; o >>= 1) s += __shfl_xor_sync(0xffffffffu, s, o);
    if (lane == 0) sred[wid] = s;
    __syncthreads();
    s = sred[0];
#pragma unroll
    for (int i = 1; i < 8; i++) s += sred[i];

    const float inv = 1.0f / s;
#pragma unroll
    for (int i = 0; i < 4; i++) {
        v[i].x *= inv; v[i].y *= inv; v[i].z *= inv; v[i].w *= inv;
        p[tid + i * 256] = v[i];
    }
}

extern "C" void kernel_launch(void* const* d_in, const int* in_sizes, int n_in,
                              void* d_out, int out_size)
{
    const float* x  = (const float*)d_in[0];
    const float* Wq = (const float*)d_in[1];
    const float* Wk = (const float*)d_in[2];
    const float* Wv = (const float*)d_in[3];
    const float* Wo = (const float*)d_in[4];
    float* out = (float*)d_out;

    float *qp, *kp, *vp, *yp;
    cudaGetSymbolAddress((void**)&qp, g_Q);
    cudaGetSymbolAddress((void**)&kp, g_K);
    cudaGetSymbolAddress((void**)&vp, g_V);
    cudaGetSymbolAddress((void**)&yp, g_Y);

    const size_t ySz = (size_t)SEQ * FEAT;            // 4,194,304
    const size_t aSz = (size_t)NH * SEQ * SEQ;        // 134,217,728
    float* attn;
    if ((size_t)out_size >= ySz + aSz) {
        attn = out + ySz;
    } else {
        cudaGetSymbolAddress((void**)&attn, g_attn_fb);
    }

    // 1) QKV projections: [4096,1024] @ [1024,1024]
    sgemm128<false><<<dim3(HID / 128, SEQ / 128, 1), 256>>>(
        x, Wq, qp, SEQ, HID, FEAT, FEAT, HID, HID, 1.0f, 0, 0, 0);
    sgemm128<false><<<dim3(HID / 128, SEQ / 128, 1), 256>>>(
        x, Wk, kp, SEQ, HID, FEAT, FEAT, HID, HID, 1.0f, 0, 0, 0);
    sgemm128<false><<<dim3(HID / 128, SEQ / 128, 1), 256>>>(
        x, Wv, vp, SEQ, HID, FEAT, FEAT, HID, HID, 1.0f, 0, 0, 0);

    // 2) Scores: per head, S = (Q_h @ K_h^T) / sqrt(dk). NT GEMM, z = head.
    const float alpha = 0.08838834764831845f; // 1/sqrt(128)
    sgemm128<true><<<dim3(SEQ / 128, SEQ / 128, NH), 256>>>(
        qp, kp, attn, SEQ, SEQ, DK, HID, HID, SEQ, alpha,
        (size_t)DK, (size_t)DK, (size_t)SEQ * SEQ);

    // 3) Softmax in place on attn
    softmax_rows<<<NH * SEQ, 256>>>(attn);

    // 4) PV: per head, Yh = attn_h @ V_h. NN GEMM, N = 128.
    sgemm128<false><<<dim3(DK / 128, SEQ / 128, NH), 256>>>(
        attn, vp, yp, SEQ, DK, SEQ, SEQ, HID, HID, 1.0f,
        (size_t)SEQ * SEQ, (size_t)DK, (size_t)DK);

    // 5) Output projection: y = Y @ Wo
    sgemm128<false><<<dim3(FEAT / 128, SEQ / 128, 1), 256>>>(
        yp, Wo, out, SEQ, FEAT, HID, HID, FEAT, FEAT, 1.0f, 0, 0, 0);
}

// round 5
// speedup vs baseline: 2.0528x; 2.0528x over previous
#include <cuda_runtime.h>
#include <cuda_fp16.h>
#include <cstdint>
#include <math.h>

#define SEQ 4096
#define FEAT 1024
#define HID 1024
#define NH 8
#define DK 128

// ---------------------------------------------------------------------------
// Device-global scratch (allocation-free per harness rules)
// ---------------------------------------------------------------------------
__device__ __half g_xh[(size_t)SEQ * FEAT], g_xl[(size_t)SEQ * FEAT];
__device__ __half g_wqth[(size_t)HID * FEAT], g_wqtl[(size_t)HID * FEAT];
__device__ __half g_wkth[(size_t)HID * FEAT], g_wktl[(size_t)HID * FEAT];
__device__ __half g_wvth[(size_t)HID * FEAT], g_wvtl[(size_t)HID * FEAT];
__device__ __half g_woth[(size_t)FEAT * HID], g_wotl[(size_t)FEAT * HID];
__device__ __half g_qh[(size_t)SEQ * HID], g_ql[(size_t)SEQ * HID];
__device__ __half g_kh[(size_t)SEQ * HID], g_kl[(size_t)SEQ * HID];
__device__ float  g_vf[(size_t)SEQ * HID];
__device__ __half g_vth[(size_t)HID * SEQ], g_vtl[(size_t)HID * SEQ];
__device__ __half g_ph[(size_t)NH * SEQ * SEQ], g_pl[(size_t)NH * SEQ * SEQ];
__device__ __half g_yh[(size_t)SEQ * HID], g_yl[(size_t)SEQ * HID];
__device__ float  g_attn_fb[(size_t)NH * SEQ * SEQ];

// ---------------------------------------------------------------------------
// PTX helpers (all arch-agnostic: cp.async sm_80+, ldmatrix sm_75+, mma sm_80+)
// ---------------------------------------------------------------------------
__device__ __forceinline__ uint32_t s2u(const void* p) {
    uint32_t a;
    asm("{ .reg .u64 t; cvta.to.shared.u64 t, %1; cvt.u32.u64 %0, t; }" : "=r"(a) : "l"(p));
    return a;
}
__device__ __forceinline__ void cpa16(uint32_t d, const void* s) {
    asm volatile("cp.async.cg.shared.global [%0], [%1], 16;" :: "r"(d), "l"(s));
}
__device__ __forceinline__ void cpcommit() { asm volatile("cp.async.commit_group;"); }
template <int N>
__device__ __forceinline__ void cpwait() { asm volatile("cp.async.wait_group %0;" :: "n"(N)); }

__device__ __forceinline__ void ldm4(uint32_t& r0, uint32_t& r1, uint32_t& r2, uint32_t& r3, uint32_t a) {
    asm volatile("ldmatrix.sync.aligned.m8n8.x4.shared.b16 {%0,%1,%2,%3}, [%4];"
                 : "=r"(r0), "=r"(r1), "=r"(r2), "=r"(r3) : "r"(a));
}
__device__ __forceinline__ void mma16816(float* c, const uint32_t* a, const uint32_t* b) {
    asm volatile(
        "mma.sync.aligned.m16n8k16.row.col.f32.f16.f16.f32 "
        "{%0,%1,%2,%3}, {%4,%5,%6,%7}, {%8,%9}, {%0,%1,%2,%3};"
        : "+f"(c[0]), "+f"(c[1]), "+f"(c[2]), "+f"(c[3])
        : "r"(a[0]), "r"(a[1]), "r"(a[2]), "r"(a[3]), "r"(b[0]), "r"(b[1]));
}

// ---------------------------------------------------------------------------
// Tensor-core split-fp16 GEMM: C[M,N] = alpha * (Ah+Al)[M,K] @ (Bh+Bl)[N,K]^T
// CTA tile 128x128, BK=32, 8 warps (2x4), double-buffered cp.async.
// Smem tiles padded to 80B rows (conflict-free ldmatrix, no swizzle needed).
// MODE 0: write fp32 C. MODE 1: write fp16 hi/lo pair.
// ---------------------------------------------------------------------------
#define LDT_B 80                      // bytes per smem tile row (32 halves + pad)
#define TILE_B (128 * LDT_B)          // 10240 bytes per tile
#define STAGE_B (4 * TILE_B)          // Ah, Al, Bh, Bl
#define SMEMSZ (2 * STAGE_B)          // 81920

template <int MODE>
__global__ void __launch_bounds__(256) gemm_mma(
    const __half* __restrict__ Ah, const __half* __restrict__ Al,
    const __half* __restrict__ Bh, const __half* __restrict__ Bl,
    float* __restrict__ Cf, __half* __restrict__ Ch, __half* __restrict__ Cl,
    int K, int lda, int ldb, int ldc, float alpha,
    size_t sA, size_t sB, size_t sC)
{
    extern __shared__ char sm[];
    const uint32_t smb = s2u(sm);

    const int tid = threadIdx.x;
    const int wid = tid >> 5;
    const int lane = tid & 31;
    const int warp_m = wid & 1;       // 0..1 -> 64 rows
    const int warp_n = wid >> 1;      // 0..3 -> 32 cols

    Ah += blockIdx.z * sA; Al += blockIdx.z * sA;
    Bh += blockIdx.z * sB; Bl += blockIdx.z * sB;
    const size_t cOff = blockIdx.z * sC;

    const int bm = blockIdx.y * 128;
    const int bn = blockIdx.x * 128;

    // cp.async indices: j = tid + s*256 -> row=j>>2, 16B seg=j&3
    const int c_row = tid >> 2;
    const int c_seg = tid & 3;

    // ldmatrix lane offsets
    const uint32_t aoff = (uint32_t)(((lane & 7) + ((lane >> 3) & 1) * 8) * LDT_B + (lane >> 4) * 16);
    const uint32_t boff = (uint32_t)(((lane >> 4) * 8 + (lane & 7)) * LDT_B + ((lane >> 3) & 1) * 16);

    float acc[4][4][4];
#pragma unroll
    for (int i = 0; i < 4; i++)
#pragma unroll
        for (int j = 0; j < 4; j++)
#pragma unroll
            for (int q = 0; q < 4; q++) acc[i][j][q] = 0.0f;

    const int nch = K >> 5;

    // chunk loader
    auto load_chunk = [&](int stage, int kb) {
        const uint32_t sb = smb + stage * STAGE_B;
#pragma unroll
        for (int s = 0; s < 2; s++) {
            const int row = c_row + s * 64;
            const uint32_t so = (uint32_t)(row * LDT_B + c_seg * 16);
            const size_t go = (size_t)row * lda + kb + c_seg * 8;
            cpa16(sb + so,              Ah + (size_t)bm * lda + go);
            cpa16(sb + TILE_B + so,     Al + (size_t)bm * lda + go);
            const size_t gob = (size_t)row * ldb + kb + c_seg * 8;
            cpa16(sb + 2 * TILE_B + so, Bh + (size_t)bn * ldb + gob);
            cpa16(sb + 3 * TILE_B + so, Bl + (size_t)bn * ldb + gob);
        }
        cpcommit();
    };

    load_chunk(0, 0);

    for (int c = 0; c < nch; c++) {
        if (c + 1 < nch) { load_chunk((c + 1) & 1, (c + 1) << 5); cpwait<1>(); }
        else             { cpwait<0>(); }
        __syncthreads();

        const uint32_t sb = smb + (c & 1) * STAGE_B;
        const uint32_t aH = sb + (uint32_t)(warp_m * 64) * LDT_B;
        const uint32_t aL = aH + TILE_B;
        const uint32_t bH = sb + 2 * TILE_B + (uint32_t)(warp_n * 32) * LDT_B;
        const uint32_t bL = bH + TILE_B;

#pragma unroll
        for (int ks = 0; ks < 2; ks++) {
            const uint32_t kb2 = ks * 32;   // 16 halves = 32B
            uint32_t A[4][4], B[4][2], BL[4][2];
#pragma unroll
            for (int mt = 0; mt < 4; mt++)
                ldm4(A[mt][0], A[mt][1], A[mt][2], A[mt][3],
                     aH + (uint32_t)(mt * 16) * LDT_B + aoff + kb2);
#pragma unroll
            for (int p = 0; p < 2; p++) {
                uint32_t r0, r1, r2, r3;
                ldm4(r0, r1, r2, r3, bH + (uint32_t)(p * 16) * LDT_B + boff + kb2);
                B[p * 2][0] = r0; B[p * 2][1] = r1;
                B[p * 2 + 1][0] = r2; B[p * 2 + 1][1] = r3;
            }
#pragma unroll
            for (int p = 0; p < 2; p++) {
                uint32_t r0, r1, r2, r3;
                ldm4(r0, r1, r2, r3, bL + (uint32_t)(p * 16) * LDT_B + boff + kb2);
                BL[p * 2][0] = r0; BL[p * 2][1] = r1;
                BL[p * 2 + 1][0] = r2; BL[p * 2 + 1][1] = r3;
            }
            // hi*hi
#pragma unroll
            for (int mt = 0; mt < 4; mt++)
#pragma unroll
                for (int nt = 0; nt < 4; nt++)
                    mma16816(acc[mt][nt], A[mt], B[nt]);
            // hi*lo
#pragma unroll
            for (int mt = 0; mt < 4; mt++)
#pragma unroll
                for (int nt = 0; nt < 4; nt++)
                    mma16816(acc[mt][nt], A[mt], BL[nt]);
            // lo*hi (reload A regs with Al)
#pragma unroll
            for (int mt = 0; mt < 4; mt++)
                ldm4(A[mt][0], A[mt][1], A[mt][2], A[mt][3],
                     aL + (uint32_t)(mt * 16) * LDT_B + aoff + kb2);
#pragma unroll
            for (int mt = 0; mt < 4; mt++)
#pragma unroll
                for (int nt = 0; nt < 4; nt++)
                    mma16816(acc[mt][nt], A[mt], B[nt]);
        }
        __syncthreads();
    }

    // Epilogue
    const int g = lane >> 2;
    const int tq = lane & 3;
#pragma unroll
    for (int mt = 0; mt < 4; mt++) {
        const int row0 = bm + warp_m * 64 + mt * 16 + g;
#pragma unroll
        for (int nt = 0; nt < 4; nt++) {
            const int col = bn + warp_n * 32 + nt * 8 + tq * 2;
            const float v0 = acc[mt][nt][0] * alpha;
            const float v1 = acc[mt][nt][1] * alpha;
            const float v2 = acc[mt][nt][2] * alpha;
            const float v3 = acc[mt][nt][3] * alpha;
            if (MODE == 0) {
                float2* p0 = reinterpret_cast<float2*>(Cf + cOff + (size_t)row0 * ldc + col);
                float2* p1 = reinterpret_cast<float2*>(Cf + cOff + (size_t)(row0 + 8) * ldc + col);
                *p0 = make_float2(v0, v1);
                *p1 = make_float2(v2, v3);
            } else {
                const __half h0 = __float2half_rn(v0), h1 = __float2half_rn(v1);
                const __half h2 = __float2half_rn(v2), h3 = __float2half_rn(v3);
                const __half l0 = __float2half_rn(v0 - __half2float(h0));
                const __half l1 = __float2half_rn(v1 - __half2float(h1));
                const __half l2 = __float2half_rn(v2 - __half2float(h2));
                const __half l3 = __float2half_rn(v3 - __half2float(h3));
                *reinterpret_cast<__half2*>(Ch + cOff + (size_t)row0 * ldc + col) = __halves2half2(h0, h1);
                *reinterpret_cast<__half2*>(Ch + cOff + (size_t)(row0 + 8) * ldc + col) = __halves2half2(h2, h3);
                *reinterpret_cast<__half2*>(Cl + cOff + (size_t)row0 * ldc + col) = __halves2half2(l0, l1);
                *reinterpret_cast<__half2*>(Cl + cOff + (size_t)(row0 + 8) * ldc + col) = __halves2half2(l2, l3);
            }
        }
    }
}

// ---------------------------------------------------------------------------
// Prep kernels
// ---------------------------------------------------------------------------
__global__ void convert_split(const float* __restrict__ in,
                              __half* __restrict__ oh, __half* __restrict__ ol, int n4)
{
    const int i = blockIdx.x * blockDim.x + threadIdx.x;
    if (i >= n4) return;
    const float4 v = reinterpret_cast<const float4*>(in)[i];
    const __half h0 = __float2half_rn(v.x), h1 = __float2half_rn(v.y);
    const __half h2 = __float2half_rn(v.z), h3 = __float2half_rn(v.w);
    const __half l0 = __float2half_rn(v.x - __half2float(h0));
    const __half l1 = __float2half_rn(v.y - __half2float(h1));
    const __half l2 = __float2half_rn(v.z - __half2float(h2));
    const __half l3 = __float2half_rn(v.w - __half2float(h3));
    __half2 ha = __halves2half2(h0, h1), hb = __halves2half2(h2, h3);
    __half2 la = __halves2half2(l0, l1), lb = __halves2half2(l2, l3);
    uint2 uh, ul;
    uh.x = *reinterpret_cast<uint32_t*>(&ha); uh.y = *reinterpret_cast<uint32_t*>(&hb);
    ul.x = *reinterpret_cast<uint32_t*>(&la); ul.y = *reinterpret_cast<uint32_t*>(&lb);
    reinterpret_cast<uint2*>(oh)[i] = uh;
    reinterpret_cast<uint2*>(ol)[i] = ul;
}

// in: [R][C] fp32  ->  out hi/lo: [C][R] fp16
__global__ void transpose_split(const float* __restrict__ in,
                                __half* __restrict__ oh, __half* __restrict__ ol, int R, int C)
{
    __shared__ float t[32][33];
    const int bc = blockIdx.x * 32, br = blockIdx.y * 32;
    const int x = threadIdx.x, y = threadIdx.y;
#pragma unroll
    for (int j = 0; j < 32; j += 8)
        t[y + j][x] = in[(size_t)(br + y + j) * C + bc + x];
    __syncthreads();
#pragma unroll
    for (int j = 0; j < 32; j += 8) {
        const float v = t[x][y + j];
        const __half h = __float2half_rn(v);
        const size_t o = (size_t)(bc + y + j) * R + br + x;
        oh[o] = h;
        ol[o] = __float2half_rn(v - __half2float(h));
    }
}

// ---------------------------------------------------------------------------
// Row softmax (in place, fp32) fused with fp16 hi/lo split for PV
// ---------------------------------------------------------------------------
__global__ void softmax_split(float* __restrict__ attn,
                              __half* __restrict__ ph, __half* __restrict__ pl)
{
    __shared__ float sred[8];
    const size_t row = blockIdx.x;
    float4* p = reinterpret_cast<float4*>(attn + row * (size_t)SEQ);
    const int tid = threadIdx.x;
    const int lane = tid & 31, wid = tid >> 5;

    float4 v[4];
    float m = -1e30f;
#pragma unroll
    for (int i = 0; i < 4; i++) {
        v[i] = p[tid + i * 256];
        m = fmaxf(m, fmaxf(fmaxf(v[i].x, v[i].y), fmaxf(v[i].z, v[i].w)));
    }
#pragma unroll
    for (int o = 16; o; o >>= 1) m = fmaxf(m, __shfl_xor_sync(0xffffffffu, m, o));
    if (lane == 0) sred[wid] = m;
    __syncthreads();
    m = sred[0];
#pragma unroll
    for (int i = 1; i < 8; i++) m = fmaxf(m, sred[i]);

    float s = 0.0f;
#pragma unroll
    for (int i = 0; i < 4; i++) {
        v[i].x = __expf(v[i].x - m); v[i].y = __expf(v[i].y - m);
        v[i].z = __expf(v[i].z - m); v[i].w = __expf(v[i].w - m);
        s += v[i].x + v[i].y + v[i].z + v[i].w;
    }
    __syncthreads();
#pragma unroll
    for (int o = 16; o; o >>= 1) s += __shfl_xor_sync(0xffffffffu, s, o);
    if (lane == 0) sred[wid] = s;
    __syncthreads();
    s = sred[0];
#pragma unroll
    for (int i = 1; i < 8; i++) s += sred[i];

    const float inv = 1.0f / s;
    const size_t base = row * (size_t)SEQ;
#pragma unroll
    for (int i = 0; i < 4; i++) {
        v[i].x *= inv; v[i].y *= inv; v[i].z *= inv; v[i].w *= inv;
        p[tid + i * 256] = v[i];
        const __half h0 = __float2half_rn(v[i].x), h1 = __float2half_rn(v[i].y);
        const __half h2 = __float2half_rn(v[i].z), h3 = __float2half_rn(v[i].w);
        const __half l0 = __float2half_rn(v[i].x - __half2float(h0));
        const __half l1 = __float2half_rn(v[i].y - __half2float(h1));
        const __half l2 = __float2half_rn(v[i].z - __half2float(h2));
        const __half l3 = __float2half_rn(v[i].w - __half2float(h3));
        __half2 ha = __halves2half2(h0, h1), hb = __halves2half2(h2, h3);
        __half2 la = __halves2half2(l0, l1), lb = __halves2half2(l2, l3);
        uint2 uh, ul;
        uh.x = *reinterpret_cast<const uint32_t*>(&ha); uh.y = *reinterpret_cast<const uint32_t*>(&hb);
        ul.x = *reinterpret_cast<const uint32_t*>(&la); ul.y = *reinterpret_cast<const uint32_t*>(&lb);
        const size_t e = base + (size_t)(tid + i * 256) * 4;
        *reinterpret_cast<uint2*>(ph + e) = uh;
        *reinterpret_cast<uint2*>(pl + e) = ul;
    }
}

// ---------------------------------------------------------------------------
extern "C" void kernel_launch(void* const* d_in, const int* in_sizes, int n_in,
                              void* d_out, int out_size)
{
    const float* x  = (const float*)d_in[0];
    const float* Wq = (const float*)d_in[1];
    const float* Wk = (const float*)d_in[2];
    const float* Wv = (const float*)d_in[3];
    const float* Wo = (const float*)d_in[4];
    float* out = (float*)d_out;

    cudaFuncSetAttribute(gemm_mma<0>, cudaFuncAttributeMaxDynamicSharedMemorySize, SMEMSZ);
    cudaFuncSetAttribute(gemm_mma<1>, cudaFuncAttributeMaxDynamicSharedMemorySize, SMEMSZ);

    __half *xh, *xl, *wqth, *wqtl, *wkth, *wktl, *wvth, *wvtl, *woth, *wotl;
    __half *qh, *ql, *kh, *kl, *vth, *vtl, *ph, *pl, *yh, *yl;
    float* vf;
    cudaGetSymbolAddress((void**)&xh, g_xh);     cudaGetSymbolAddress((void**)&xl, g_xl);
    cudaGetSymbolAddress((void**)&wqth, g_wqth); cudaGetSymbolAddress((void**)&wqtl, g_wqtl);
    cudaGetSymbolAddress((void**)&wkth, g_wkth); cudaGetSymbolAddress((void**)&wktl, g_wktl);
    cudaGetSymbolAddress((void**)&wvth, g_wvth); cudaGetSymbolAddress((void**)&wvtl, g_wvtl);
    cudaGetSymbolAddress((void**)&woth, g_woth); cudaGetSymbolAddress((void**)&wotl, g_wotl);
    cudaGetSymbolAddress((void**)&qh, g_qh);     cudaGetSymbolAddress((void**)&ql, g_ql);
    cudaGetSymbolAddress((void**)&kh, g_kh);     cudaGetSymbolAddress((void**)&kl, g_kl);
    cudaGetSymbolAddress((void**)&vf, g_vf);
    cudaGetSymbolAddress((void**)&vth, g_vth);   cudaGetSymbolAddress((void**)&vtl, g_vtl);
    cudaGetSymbolAddress((void**)&ph, g_ph);     cudaGetSymbolAddress((void**)&pl, g_pl);
    cudaGetSymbolAddress((void**)&yh, g_yh);     cudaGetSymbolAddress((void**)&yl, g_yl);

    const size_t ySz = (size_t)SEQ * FEAT;
    const size_t aSz = (size_t)NH * SEQ * SEQ;
    float* attn;
    if ((size_t)out_size >= ySz + aSz) attn = out + ySz;
    else cudaGetSymbolAddress((void**)&attn, g_attn_fb);

    // Prep: split x, transpose+split weights
    convert_split<<<(SEQ * FEAT / 4 + 255) / 256, 256>>>(x, xh, xl, SEQ * FEAT / 4);
    dim3 tb(32, 8);
    transpose_split<<<dim3(HID / 32, FEAT / 32), tb>>>(Wq, wqth, wqtl, FEAT, HID);
    transpose_split<<<dim3(HID / 32, FEAT / 32), tb>>>(Wk, wkth, wktl, FEAT, HID);
    transpose_split<<<dim3(HID / 32, FEAT / 32), tb>>>(Wv, wvth, wvtl, FEAT, HID);
    transpose_split<<<dim3(FEAT / 32, HID / 32), tb>>>(Wo, woth, wotl, HID, FEAT);

    // Q, K projections -> fp16 hi/lo
    gemm_mma<1><<<dim3(HID / 128, SEQ / 128, 1), 256, SMEMSZ>>>(
        xh, xl, wqth, wqtl, nullptr, qh, ql, FEAT, FEAT, FEAT, HID, 1.0f, 0, 0, 0);
    gemm_mma<1><<<dim3(HID / 128, SEQ / 128, 1), 256, SMEMSZ>>>(
        xh, xl, wkth, wktl, nullptr, kh, kl, FEAT, FEAT, FEAT, HID, 1.0f, 0, 0, 0);
    // V projection -> fp32, then transpose+split to [HID][SEQ]
    gemm_mma<0><<<dim3(HID / 128, SEQ / 128, 1), 256, SMEMSZ>>>(
        xh, xl, wvth, wvtl, vf, nullptr, nullptr, FEAT, FEAT, FEAT, HID, 1.0f, 0, 0, 0);
    transpose_split<<<dim3(HID / 32, SEQ / 32), tb>>>(vf, vth, vtl, SEQ, HID);

    // Scores: per head z: attn = alpha * Q_h @ K_h^T  (fp32 out)
    const float alpha = 0.08838834764831845f; // 1/sqrt(128)
    gemm_mma<0><<<dim3(SEQ / 128, SEQ / 128, NH), 256, SMEMSZ>>>(
        qh, ql, kh, kl, attn, nullptr, nullptr, DK, HID, HID, SEQ, alpha,
        (size_t)DK, (size_t)DK, (size_t)SEQ * SEQ);

    // Softmax in place (fp32 attn output) + fp16 hi/lo split for PV
    softmax_split<<<NH * SEQ, 256>>>(attn, ph, pl);

    // PV: per head z: Y_h = P_h @ V_h  (Vt: [HID][SEQ])
    gemm_mma<1><<<dim3(1, SEQ / 128, NH), 256, SMEMSZ>>>(
        ph, pl, vth, vtl, nullptr, yh, yl, SEQ, SEQ, SEQ, HID, 1.0f,
        (size_t)SEQ * SEQ, (size_t)DK * SEQ, (size_t)DK);

    // Output projection: out = Y @ Wo  (fp32)
    gemm_mma<0><<<dim3(FEAT / 128, SEQ / 128, 1), 256, SMEMSZ>>>(
        yh, yl, woth, wotl, out, nullptr, nullptr, HID, HID, HID, FEAT, 1.0f, 0, 0, 0);
}

// round 6
// speedup vs baseline: 2.7103x; 1.3203x over previous
#include <cuda_runtime.h>
#include <cuda_fp16.h>
#include <cstdint>
#include <math.h>

#define SEQ 4096
#define FEAT 1024
#define HID 1024
#define NH 8
#define DK 128
#define NROWS (NH * SEQ)

// ---------------------------------------------------------------------------
// Device-global scratch (allocation-free per harness rules)
// ---------------------------------------------------------------------------
__device__ __half g_xh[(size_t)SEQ * FEAT], g_xl[(size_t)SEQ * FEAT];
__device__ __half g_wqth[(size_t)HID * FEAT], g_wqtl[(size_t)HID * FEAT];
__device__ __half g_wkth[(size_t)HID * FEAT], g_wktl[(size_t)HID * FEAT];
__device__ __half g_wvth[(size_t)HID * FEAT], g_wvtl[(size_t)HID * FEAT];
__device__ __half g_woth[(size_t)FEAT * HID], g_wotl[(size_t)FEAT * HID];
__device__ __half g_qh[(size_t)SEQ * HID], g_ql[(size_t)SEQ * HID];
__device__ __half g_kh[(size_t)SEQ * HID], g_kl[(size_t)SEQ * HID];
__device__ float  g_vf[(size_t)SEQ * HID];
__device__ __half g_vth[(size_t)HID * SEQ], g_vtl[(size_t)HID * SEQ];
__device__ __half g_yh[(size_t)SEQ * HID], g_yl[(size_t)SEQ * HID];
__device__ float  g_stats[2 * NROWS];
__device__ float  g_attn_fb[(size_t)NH * SEQ * SEQ];

// ---------------------------------------------------------------------------
// PTX helpers (arch-agnostic: cp.async sm_80+, ldmatrix sm_75+, mma sm_80+)
// ---------------------------------------------------------------------------
__device__ __forceinline__ uint32_t s2u(const void* p) {
    uint32_t a;
    asm("{ .reg .u64 t; cvta.to.shared.u64 t, %1; cvt.u32.u64 %0, t; }" : "=r"(a) : "l"(p));
    return a;
}
__device__ __forceinline__ void cpa16(uint32_t d, const void* s) {
    asm volatile("cp.async.cg.shared.global [%0], [%1], 16;" :: "r"(d), "l"(s));
}
__device__ __forceinline__ void cpcommit() { asm volatile("cp.async.commit_group;"); }
template <int N>
__device__ __forceinline__ void cpwait() { asm volatile("cp.async.wait_group %0;" :: "n"(N)); }

__device__ __forceinline__ void ldm4(uint32_t& r0, uint32_t& r1, uint32_t& r2, uint32_t& r3, uint32_t a) {
    asm volatile("ldmatrix.sync.aligned.m8n8.x4.shared.b16 {%0,%1,%2,%3}, [%4];"
                 : "=r"(r0), "=r"(r1), "=r"(r2), "=r"(r3) : "r"(a));
}
__device__ __forceinline__ void mma16816(float* c, const uint32_t* a, const uint32_t* b) {
    asm volatile(
        "mma.sync.aligned.m16n8k16.row.col.f32.f16.f16.f32 "
        "{%0,%1,%2,%3}, {%4,%5,%6,%7}, {%8,%9}, {%0,%1,%2,%3};"
        : "+f"(c[0]), "+f"(c[1]), "+f"(c[2]), "+f"(c[3])
        : "r"(a[0]), "r"(a[1]), "r"(a[2]), "r"(a[3]), "r"(b[0]), "r"(b[1]));
}

// ---------------------------------------------------------------------------
// Split-fp16 tensor-core GEMM: C[M,N] = alpha * A[M,K] @ B[N,K]^T
// TERMS=3: (Ah+Al)·Bh + Ah·Bl   (full ~2^-22 precision)
// TERMS=2: (Ah+Al)·Bh           (B rounded to fp16, ~2^-12)
// MODE 0: fp32 C.  MODE 1: fp16 hi/lo C pair.
// ---------------------------------------------------------------------------
#define LDT_B 80
#define TILE_B (128 * LDT_B)
#define STAGE_B (4 * TILE_B)
#define SMEMSZ (2 * STAGE_B)

template <int MODE, int TERMS>
__global__ void __launch_bounds__(256) gemm_mma(
    const __half* __restrict__ Ah, const __half* __restrict__ Al,
    const __half* __restrict__ Bh, const __half* __restrict__ Bl,
    float* __restrict__ Cf, __half* __restrict__ Ch, __half* __restrict__ Cl,
    int K, int lda, int ldb, int ldc, float alpha,
    size_t sA, size_t sB, size_t sC)
{
    extern __shared__ char sm[];
    const uint32_t smb = s2u(sm);

    const int tid = threadIdx.x;
    const int wid = tid >> 5;
    const int lane = tid & 31;
    const int warp_m = wid & 1;
    const int warp_n = wid >> 1;

    Ah += blockIdx.z * sA; Al += blockIdx.z * sA;
    Bh += blockIdx.z * sB; Bl += blockIdx.z * sB;
    const size_t cOff = blockIdx.z * sC;

    const int bm = blockIdx.y * 128;
    const int bn = blockIdx.x * 128;

    const int c_row = tid >> 2;
    const int c_seg = tid & 3;

    const uint32_t aoff = (uint32_t)(((lane & 7) + ((lane >> 3) & 1) * 8) * LDT_B + (lane >> 4) * 16);
    const uint32_t boff = (uint32_t)(((lane >> 4) * 8 + (lane & 7)) * LDT_B + ((lane >> 3) & 1) * 16);

    float acc[4][4][4];
#pragma unroll
    for (int i = 0; i < 4; i++)
#pragma unroll
        for (int j = 0; j < 4; j++)
#pragma unroll
            for (int q = 0; q < 4; q++) acc[i][j][q] = 0.0f;

    const int nch = K >> 5;

    auto load_chunk = [&](int stage, int kb) {
        const uint32_t sb = smb + stage * STAGE_B;
#pragma unroll
        for (int s = 0; s < 2; s++) {
            const int row = c_row + s * 64;
            const uint32_t so = (uint32_t)(row * LDT_B + c_seg * 16);
            const size_t go = (size_t)row * lda + kb + c_seg * 8;
            cpa16(sb + so,              Ah + (size_t)bm * lda + go);
            cpa16(sb + TILE_B + so,     Al + (size_t)bm * lda + go);
            const size_t gob = (size_t)row * ldb + kb + c_seg * 8;
            cpa16(sb + 2 * TILE_B + so, Bh + (size_t)bn * ldb + gob);
            if constexpr (TERMS == 3)
                cpa16(sb + 3 * TILE_B + so, Bl + (size_t)bn * ldb + gob);
        }
        cpcommit();
    };

    load_chunk(0, 0);

    for (int c = 0; c < nch; c++) {
        if (c + 1 < nch) { load_chunk((c + 1) & 1, (c + 1) << 5); cpwait<1>(); }
        else             { cpwait<0>(); }
        __syncthreads();

        const uint32_t sb = smb + (c & 1) * STAGE_B;
        const uint32_t aH = sb + (uint32_t)(warp_m * 64) * LDT_B;
        const uint32_t aL = aH + TILE_B;
        const uint32_t bH = sb + 2 * TILE_B + (uint32_t)(warp_n * 32) * LDT_B;
        const uint32_t bL = bH + TILE_B;

#pragma unroll
        for (int ks = 0; ks < 2; ks++) {
            const uint32_t kb2 = ks * 32;
            uint32_t A[4][4], B[4][2];
#pragma unroll
            for (int mt = 0; mt < 4; mt++)
                ldm4(A[mt][0], A[mt][1], A[mt][2], A[mt][3],
                     aH + (uint32_t)(mt * 16) * LDT_B + aoff + kb2);
#pragma unroll
            for (int p = 0; p < 2; p++) {
                uint32_t r0, r1, r2, r3;
                ldm4(r0, r1, r2, r3, bH + (uint32_t)(p * 16) * LDT_B + boff + kb2);
                B[p * 2][0] = r0; B[p * 2][1] = r1;
                B[p * 2 + 1][0] = r2; B[p * 2 + 1][1] = r3;
            }
#pragma unroll
            for (int mt = 0; mt < 4; mt++)
#pragma unroll
                for (int nt = 0; nt < 4; nt++)
                    mma16816(acc[mt][nt], A[mt], B[nt]);

            if constexpr (TERMS == 3) {
                uint32_t BL[4][2];
#pragma unroll
                for (int p = 0; p < 2; p++) {
                    uint32_t r0, r1, r2, r3;
                    ldm4(r0, r1, r2, r3, bL + (uint32_t)(p * 16) * LDT_B + boff + kb2);
                    BL[p * 2][0] = r0; BL[p * 2][1] = r1;
                    BL[p * 2 + 1][0] = r2; BL[p * 2 + 1][1] = r3;
                }
#pragma unroll
                for (int mt = 0; mt < 4; mt++)
#pragma unroll
                    for (int nt = 0; nt < 4; nt++)
                        mma16816(acc[mt][nt], A[mt], BL[nt]);
            }
            // lo*hi: reload A regs with Al
#pragma unroll
            for (int mt = 0; mt < 4; mt++)
                ldm4(A[mt][0], A[mt][1], A[mt][2], A[mt][3],
                     aL + (uint32_t)(mt * 16) * LDT_B + aoff + kb2);
#pragma unroll
            for (int mt = 0; mt < 4; mt++)
#pragma unroll
                for (int nt = 0; nt < 4; nt++)
                    mma16816(acc[mt][nt], A[mt], B[nt]);
        }
        __syncthreads();
    }

    const int g = lane >> 2;
    const int tq = lane & 3;
#pragma unroll
    for (int mt = 0; mt < 4; mt++) {
        const int row0 = bm + warp_m * 64 + mt * 16 + g;
#pragma unroll
        for (int nt = 0; nt < 4; nt++) {
            const int col = bn + warp_n * 32 + nt * 8 + tq * 2;
            const float v0 = acc[mt][nt][0] * alpha;
            const float v1 = acc[mt][nt][1] * alpha;
            const float v2 = acc[mt][nt][2] * alpha;
            const float v3 = acc[mt][nt][3] * alpha;
            if (MODE == 0) {
                *reinterpret_cast<float2*>(Cf + cOff + (size_t)row0 * ldc + col) = make_float2(v0, v1);
                *reinterpret_cast<float2*>(Cf + cOff + (size_t)(row0 + 8) * ldc + col) = make_float2(v2, v3);
            } else {
                const __half h0 = __float2half_rn(v0), h1 = __float2half_rn(v1);
                const __half h2 = __float2half_rn(v2), h3 = __float2half_rn(v3);
                const __half l0 = __float2half_rn(v0 - __half2float(h0));
                const __half l1 = __float2half_rn(v1 - __half2float(h1));
                const __half l2 = __float2half_rn(v2 - __half2float(h2));
                const __half l3 = __float2half_rn(v3 - __half2float(h3));
                *reinterpret_cast<__half2*>(Ch + cOff + (size_t)row0 * ldc + col) = __halves2half2(h0, h1);
                *reinterpret_cast<__half2*>(Ch + cOff + (size_t)(row0 + 8) * ldc + col) = __halves2half2(h2, h3);
                *reinterpret_cast<__half2*>(Cl + cOff + (size_t)row0 * ldc + col) = __halves2half2(l0, l1);
                *reinterpret_cast<__half2*>(Cl + cOff + (size_t)(row0 + 8) * ldc + col) = __halves2half2(l2, l3);
            }
        }
    }
}

// ---------------------------------------------------------------------------
// Online-softmax row stats: per row of the 8x4096x4096 scaled scores,
// compute m = rowmax, inv = 1/sum(exp(s-m)). One warp per row.
// ---------------------------------------------------------------------------
__global__ void __launch_bounds__(256) reduce_rows(const float* __restrict__ attn,
                                                   float* __restrict__ stats)
{
    const int wid = threadIdx.x >> 5;
    const int lane = threadIdx.x & 31;
    const int row = blockIdx.x * 8 + wid;
    const float4* p = reinterpret_cast<const float4*>(attn + (size_t)row * SEQ);

    float m = -1e30f, s = 0.0f;
#pragma unroll
    for (int j = 0; j < 32; j++) {
        const float4 v = p[lane + j * 32];
        float cm = fmaxf(fmaxf(v.x, v.y), fmaxf(v.z, v.w));
        float nm = fmaxf(m, cm);
        s = s * __expf(m - nm) + __expf(v.x - nm) + __expf(v.y - nm)
          + __expf(v.z - nm) + __expf(v.w - nm);
        m = nm;
    }
#pragma unroll
    for (int o = 16; o; o >>= 1) {
        const float om = __shfl_xor_sync(0xffffffffu, m, o);
        const float os = __shfl_xor_sync(0xffffffffu, s, o);
        const float nm = fmaxf(m, om);
        s = s * __expf(m - nm) + os * __expf(om - nm);
        m = nm;
    }
    if (lane == 0) {
        stats[row] = m;
        stats[NROWS + row] = 1.0f / s;
    }
}

// ---------------------------------------------------------------------------
// Fused softmax-normalize + PV GEMM.
// Reads raw scaled scores (fp32), computes p = exp(s-m)*inv, writes normalized
// attn fp32 in place, and accumulates Y = P @ (Vh + Vl) via tensor cores.
// grid (1, SEQ/128, NH), block 256. 2-term: Ph*Vh + Ph*Vl.
// ---------------------------------------------------------------------------
#define PV_TILE (128 * LDT_B)
#define PV_SMEM (6 * PV_TILE)

__global__ void __launch_bounds__(256) pv_fused(
    float* __restrict__ attn, const float* __restrict__ stats,
    const __half* __restrict__ vth, const __half* __restrict__ vtl,
    __half* __restrict__ yh, __half* __restrict__ yl)
{
    extern __shared__ char sm[];
    const uint32_t smb = s2u(sm);
    __shared__ float sm_m[128], sm_inv[128];

    const int tid = threadIdx.x;
    const int wid = tid >> 5, lane = tid & 31;
    const int warp_m = wid & 1, warp_n = wid >> 1;
    const int z = blockIdx.z;
    const int bm = blockIdx.y * 128;

    float* ab = attn + (size_t)z * SEQ * SEQ + (size_t)bm * SEQ;
    const __half* vhb = vth + (size_t)(z * DK) * SEQ;
    const __half* vlb = vtl + (size_t)(z * DK) * SEQ;

    const int grow = z * SEQ + bm;
    if (tid < 128) {
        sm_m[tid] = stats[grow + tid];
        sm_inv[tid] = stats[NROWS + grow + tid];
    }
    __syncthreads();

    float4 pre[4];
    auto ldA = [&](int kb) {
#pragma unroll
        for (int i = 0; i < 4; i++) {
            const int idx = tid + i * 256;
            pre[i] = *reinterpret_cast<const float4*>(
                ab + (size_t)(idx >> 3) * SEQ + kb + (idx & 7) * 4);
        }
    };
    auto expsts = [&](int kb, int st) {
        const uint32_t as = smb + st * PV_TILE;
#pragma unroll
        for (int i = 0; i < 4; i++) {
            const int idx = tid + i * 256;
            const int r = idx >> 3, sg = idx & 7;
            const float m = sm_m[r], inv = sm_inv[r];
            float4 p;
            p.x = __expf(pre[i].x - m) * inv;
            p.y = __expf(pre[i].y - m) * inv;
            p.z = __expf(pre[i].z - m) * inv;
            p.w = __expf(pre[i].w - m) * inv;
            *reinterpret_cast<float4*>(ab + (size_t)r * SEQ + kb + sg * 4) = p;
            __half2 h01 = __floats2half2_rn(p.x, p.y);
            __half2 h23 = __floats2half2_rn(p.z, p.w);
            asm volatile("st.shared.v2.b32 [%0], {%1, %2};"
                         :: "r"(as + (uint32_t)(r * LDT_B + sg * 8)),
                            "r"(*reinterpret_cast<uint32_t*>(&h01)),
                            "r"(*reinterpret_cast<uint32_t*>(&h23)));
        }
    };
    auto ldV = [&](int kb, int st) {
        const uint32_t vs = smb + 2 * PV_TILE + st * 2 * PV_TILE;
#pragma unroll
        for (int i = 0; i < 2; i++) {
            const int idx = tid + i * 256;
            const int r = idx >> 2, sg = idx & 3;
            const uint32_t so = (uint32_t)(r * LDT_B + sg * 16);
            const size_t go = (size_t)r * SEQ + kb + sg * 8;
            cpa16(vs + so,           vhb + go);
            cpa16(vs + PV_TILE + so, vlb + go);
        }
        cpcommit();
    };

    const uint32_t aoff = (uint32_t)(((lane & 7) + ((lane >> 3) & 1) * 8) * LDT_B + (lane >> 4) * 16);
    const uint32_t boff = (uint32_t)(((lane >> 4) * 8 + (lane & 7)) * LDT_B + ((lane >> 3) & 1) * 16);

    float acc[4][4][4];
#pragma unroll
    for (int i = 0; i < 4; i++)
#pragma unroll
        for (int j = 0; j < 4; j++)
#pragma unroll
            for (int q = 0; q < 4; q++) acc[i][j][q] = 0.0f;

    // prologue: chunk 0
    ldA(0); ldV(0, 0);
    expsts(0, 0);

    const int nch = SEQ / 32;   // 128
    for (int c = 0; c < nch; c++) {
        if (c + 1 < nch) { ldA((c + 1) * 32); ldV((c + 1) * 32, (c + 1) & 1); cpwait<1>(); }
        else             { cpwait<0>(); }
        __syncthreads();

        const uint32_t as  = smb + (c & 1) * PV_TILE;
        const uint32_t vhs = smb + 2 * PV_TILE + (c & 1) * 2 * PV_TILE;
        const uint32_t vls = vhs + PV_TILE;

#pragma unroll
        for (int ks = 0; ks < 2; ks++) {
            const uint32_t kb2 = ks * 32;
            uint32_t A[4][4], B[4][2], BL[4][2];
#pragma unroll
            for (int mt = 0; mt < 4; mt++)
                ldm4(A[mt][0], A[mt][1], A[mt][2], A[mt][3],
                     as + (uint32_t)((warp_m * 64 + mt * 16) * LDT_B) + aoff + kb2);
#pragma unroll
            for (int p = 0; p < 2; p++) {
                uint32_t r0, r1, r2, r3;
                ldm4(r0, r1, r2, r3, vhs + (uint32_t)((warp_n * 32 + p * 16) * LDT_B) + boff + kb2);
                B[p * 2][0] = r0; B[p * 2][1] = r1;
                B[p * 2 + 1][0] = r2; B[p * 2 + 1][1] = r3;
            }
#pragma unroll
            for (int p = 0; p < 2; p++) {
                uint32_t r0, r1, r2, r3;
                ldm4(r0, r1, r2, r3, vls + (uint32_t)((warp_n * 32 + p * 16) * LDT_B) + boff + kb2);
                BL[p * 2][0] = r0; BL[p * 2][1] = r1;
                BL[p * 2 + 1][0] = r2; BL[p * 2 + 1][1] = r3;
            }
#pragma unroll
            for (int mt = 0; mt < 4; mt++)
#pragma unroll
                for (int nt = 0; nt < 4; nt++)
                    mma16816(acc[mt][nt], A[mt], B[nt]);
#pragma unroll
            for (int mt = 0; mt < 4; mt++)
#pragma unroll
                for (int nt = 0; nt < 4; nt++)
                    mma16816(acc[mt][nt], A[mt], BL[nt]);
        }
        if (c + 1 < nch) expsts((c + 1) * 32, (c + 1) & 1);
        __syncthreads();
    }

    // epilogue: fp16 hi/lo Y for the 2-term out projection
    const int g = lane >> 2, tq = lane & 3;
#pragma unroll
    for (int mt = 0; mt < 4; mt++) {
        const int row0 = bm + warp_m * 64 + mt * 16 + g;
#pragma unroll
        for (int nt = 0; nt < 4; nt++) {
            const int col = z * DK + warp_n * 32 + nt * 8 + tq * 2;
            const float v0 = acc[mt][nt][0], v1 = acc[mt][nt][1];
            const float v2 = acc[mt][nt][2], v3 = acc[mt][nt][3];
            const __half h0 = __float2half_rn(v0), h1 = __float2half_rn(v1);
            const __half h2 = __float2half_rn(v2), h3 = __float2half_rn(v3);
            const __half l0 = __float2half_rn(v0 - __half2float(h0));
            const __half l1 = __float2half_rn(v1 - __half2float(h1));
            const __half l2 = __float2half_rn(v2 - __half2float(h2));
            const __half l3 = __float2half_rn(v3 - __half2float(h3));
            *reinterpret_cast<__half2*>(yh + (size_t)row0 * HID + col) = __halves2half2(h0, h1);
            *reinterpret_cast<__half2*>(yh + (size_t)(row0 + 8) * HID + col) = __halves2half2(h2, h3);
            *reinterpret_cast<__half2*>(yl + (size_t)row0 * HID + col) = __halves2half2(l0, l1);
            *reinterpret_cast<__half2*>(yl + (size_t)(row0 + 8) * HID + col) = __halves2half2(l2, l3);
        }
    }
}

// ---------------------------------------------------------------------------
// Prep kernels
// ---------------------------------------------------------------------------
__global__ void convert_split(const float* __restrict__ in,
                              __half* __restrict__ oh, __half* __restrict__ ol, int n4)
{
    const int i = blockIdx.x * blockDim.x + threadIdx.x;
    if (i >= n4) return;
    const float4 v = reinterpret_cast<const float4*>(in)[i];
    const __half h0 = __float2half_rn(v.x), h1 = __float2half_rn(v.y);
    const __half h2 = __float2half_rn(v.z), h3 = __float2half_rn(v.w);
    const __half l0 = __float2half_rn(v.x - __half2float(h0));
    const __half l1 = __float2half_rn(v.y - __half2float(h1));
    const __half l2 = __float2half_rn(v.z - __half2float(h2));
    const __half l3 = __float2half_rn(v.w - __half2float(h3));
    __half2 ha = __halves2half2(h0, h1), hb = __halves2half2(h2, h3);
    __half2 la = __halves2half2(l0, l1), lb = __halves2half2(l2, l3);
    uint2 uh, ul;
    uh.x = *reinterpret_cast<uint32_t*>(&ha); uh.y = *reinterpret_cast<uint32_t*>(&hb);
    ul.x = *reinterpret_cast<uint32_t*>(&la); ul.y = *reinterpret_cast<uint32_t*>(&lb);
    reinterpret_cast<uint2*>(oh)[i] = uh;
    reinterpret_cast<uint2*>(ol)[i] = ul;
}

__global__ void transpose_split(const float* __restrict__ in,
                                __half* __restrict__ oh, __half* __restrict__ ol, int R, int C)
{
    __shared__ float t[32][33];
    const int bc = blockIdx.x * 32, br = blockIdx.y * 32;
    const int x = threadIdx.x, y = threadIdx.y;
#pragma unroll
    for (int j = 0; j < 32; j += 8)
        t[y + j][x] = in[(size_t)(br + y + j) * C + bc + x];
    __syncthreads();
#pragma unroll
    for (int j = 0; j < 32; j += 8) {
        const float v = t[x][y + j];
        const __half h = __float2half_rn(v);
        const size_t o = (size_t)(bc + y + j) * R + br + x;
        oh[o] = h;
        ol[o] = __float2half_rn(v - __half2float(h));
    }
}

// ---------------------------------------------------------------------------
extern "C" void kernel_launch(void* const* d_in, const int* in_sizes, int n_in,
                              void* d_out, int out_size)
{
    const float* x  = (const float*)d_in[0];
    const float* Wq = (const float*)d_in[1];
    const float* Wk = (const float*)d_in[2];
    const float* Wv = (const float*)d_in[3];
    const float* Wo = (const float*)d_in[4];
    float* out = (float*)d_out;

    cudaFuncSetAttribute(gemm_mma<0, 2>, cudaFuncAttributeMaxDynamicSharedMemorySize, SMEMSZ);
    cudaFuncSetAttribute(gemm_mma<1, 2>, cudaFuncAttributeMaxDynamicSharedMemorySize, SMEMSZ);
    cudaFuncSetAttribute(gemm_mma<0, 3>, cudaFuncAttributeMaxDynamicSharedMemorySize, SMEMSZ);
    cudaFuncSetAttribute(pv_fused, cudaFuncAttributeMaxDynamicSharedMemorySize, PV_SMEM);

    __half *xh, *xl, *wqth, *wqtl, *wkth, *wktl, *wvth, *wvtl, *woth, *wotl;
    __half *qh, *ql, *kh, *kl, *vth, *vtl, *yh, *yl;
    float *vf, *stats;
    cudaGetSymbolAddress((void**)&xh, g_xh);     cudaGetSymbolAddress((void**)&xl, g_xl);
    cudaGetSymbolAddress((void**)&wqth, g_wqth); cudaGetSymbolAddress((void**)&wqtl, g_wqtl);
    cudaGetSymbolAddress((void**)&wkth, g_wkth); cudaGetSymbolAddress((void**)&wktl, g_wktl);
    cudaGetSymbolAddress((void**)&wvth, g_wvth); cudaGetSymbolAddress((void**)&wvtl, g_wvtl);
    cudaGetSymbolAddress((void**)&woth, g_woth); cudaGetSymbolAddress((void**)&wotl, g_wotl);
    cudaGetSymbolAddress((void**)&qh, g_qh);     cudaGetSymbolAddress((void**)&ql, g_ql);
    cudaGetSymbolAddress((void**)&kh, g_kh);     cudaGetSymbolAddress((void**)&kl, g_kl);
    cudaGetSymbolAddress((void**)&vf, g_vf);
    cudaGetSymbolAddress((void**)&vth, g_vth);   cudaGetSymbolAddress((void**)&vtl, g_vtl);
    cudaGetSymbolAddress((void**)&yh, g_yh);     cudaGetSymbolAddress((void**)&yl, g_yl);
    cudaGetSymbolAddress((void**)&stats, g_stats);

    const size_t ySz = (size_t)SEQ * FEAT;
    const size_t aSz = (size_t)NH * SEQ * SEQ;
    float* attn;
    if ((size_t)out_size >= ySz + aSz) attn = out + ySz;
    else cudaGetSymbolAddress((void**)&attn, g_attn_fb);

    // Prep: split x, transpose+split weights
    convert_split<<<(SEQ * FEAT / 4 + 255) / 256, 256>>>(x, xh, xl, SEQ * FEAT / 4);
    dim3 tb(32, 8);
    transpose_split<<<dim3(HID / 32, FEAT / 32), tb>>>(Wq, wqth, wqtl, FEAT, HID);
    transpose_split<<<dim3(HID / 32, FEAT / 32), tb>>>(Wk, wkth, wktl, FEAT, HID);
    transpose_split<<<dim3(HID / 32, FEAT / 32), tb>>>(Wv, wvth, wvtl, FEAT, HID);
    transpose_split<<<dim3(FEAT / 32, HID / 32), tb>>>(Wo, woth, wotl, HID, FEAT);

    // QKV projections: 2-term (weights fp16-rounded)
    gemm_mma<1, 2><<<dim3(HID / 128, SEQ / 128, 1), 256, SMEMSZ>>>(
        xh, xl, wqth, wqtl, nullptr, qh, ql, FEAT, FEAT, FEAT, HID, 1.0f, 0, 0, 0);
    gemm_mma<1, 2><<<dim3(HID / 128, SEQ / 128, 1), 256, SMEMSZ>>>(
        xh, xl, wkth, wktl, nullptr, kh, kl, FEAT, FEAT, FEAT, HID, 1.0f, 0, 0, 0);
    gemm_mma<0, 2><<<dim3(HID / 128, SEQ / 128, 1), 256, SMEMSZ>>>(
        xh, xl, wvth, wvtl, vf, nullptr, nullptr, FEAT, FEAT, FEAT, HID, 1.0f, 0, 0, 0);
    transpose_split<<<dim3(HID / 32, SEQ / 32), tb>>>(vf, vth, vtl, SEQ, HID);

    // Scores: 3-term, fp32 scaled scores into attn buffer
    const float alpha = 0.08838834764831845f; // 1/sqrt(128)
    gemm_mma<0, 3><<<dim3(SEQ / 128, SEQ / 128, NH), 256, SMEMSZ>>>(
        qh, ql, kh, kl, attn, nullptr, nullptr, DK, HID, HID, SEQ, alpha,
        (size_t)DK, (size_t)DK, (size_t)SEQ * SEQ);

    // Row stats (online softmax)
    reduce_rows<<<NROWS / 8, 256>>>(attn, stats);

    // Fused normalize + PV
    pv_fused<<<dim3(1, SEQ / 128, NH), 256, PV_SMEM>>>(attn, stats, vth, vtl, yh, yl);

    // Output projection: 2-term
    gemm_mma<0, 2><<<dim3(FEAT / 128, SEQ / 128, 1), 256, SMEMSZ>>>(
        yh, yl, woth, wotl, out, nullptr, nullptr, HID, HID, HID, FEAT, 1.0f, 0, 0, 0);
}

// round 7
// speedup vs baseline: 2.8395x; 1.0477x over previous
#include <cuda_runtime.h>
#include <cuda_fp16.h>
#include <cstdint>
#include <math.h>

#define SEQ 4096
#define FEAT 1024
#define HID 1024
#define NH 8
#define DK 128
#define NROWS (NH * SEQ)
#define NBX 32   // score col-blocks per row

// ---------------------------------------------------------------------------
// Device-global scratch (allocation-free per harness rules)
// ---------------------------------------------------------------------------
__device__ __half g_xh[(size_t)SEQ * FEAT], g_xl[(size_t)SEQ * FEAT];
__device__ __half g_wqth[(size_t)HID * FEAT], g_wqtl[(size_t)HID * FEAT];
__device__ __half g_wkth[(size_t)HID * FEAT], g_wktl[(size_t)HID * FEAT];
__device__ __half g_wvth[(size_t)HID * FEAT], g_wvtl[(size_t)HID * FEAT];
__device__ __half g_woth[(size_t)FEAT * HID], g_wotl[(size_t)FEAT * HID];
__device__ __half g_qh[(size_t)SEQ * HID], g_ql[(size_t)SEQ * HID];
__device__ __half g_kh[(size_t)SEQ * HID], g_kl[(size_t)SEQ * HID];
__device__ float  g_vf[(size_t)SEQ * HID];
__device__ __half g_vth[(size_t)HID * SEQ], g_vtl[(size_t)HID * SEQ];
__device__ __half g_yh[(size_t)SEQ * HID], g_yl[(size_t)SEQ * HID];
__device__ float  g_stats[2 * NROWS];
__device__ float  g_pm[(size_t)NROWS * NBX], g_ps[(size_t)NROWS * NBX];
__device__ float  g_attn_fb[(size_t)NH * SEQ * SEQ];

// ---------------------------------------------------------------------------
// PTX helpers (arch-agnostic: cp.async sm_80+, ldmatrix sm_75+, mma sm_80+)
// ---------------------------------------------------------------------------
__device__ __forceinline__ uint32_t s2u(const void* p) {
    uint32_t a;
    asm("{ .reg .u64 t; cvta.to.shared.u64 t, %1; cvt.u32.u64 %0, t; }" : "=r"(a) : "l"(p));
    return a;
}
__device__ __forceinline__ void cpa16(uint32_t d, const void* s) {
    asm volatile("cp.async.cg.shared.global [%0], [%1], 16;" :: "r"(d), "l"(s));
}
__device__ __forceinline__ void cpcommit() { asm volatile("cp.async.commit_group;"); }
template <int N>
__device__ __forceinline__ void cpwait() { asm volatile("cp.async.wait_group %0;" :: "n"(N)); }

__device__ __forceinline__ void ldm4(uint32_t& r0, uint32_t& r1, uint32_t& r2, uint32_t& r3, uint32_t a) {
    asm volatile("ldmatrix.sync.aligned.m8n8.x4.shared.b16 {%0,%1,%2,%3}, [%4];"
                 : "=r"(r0), "=r"(r1), "=r"(r2), "=r"(r3) : "r"(a));
}
__device__ __forceinline__ void mma16816(float* c, const uint32_t* a, const uint32_t* b) {
    asm volatile(
        "mma.sync.aligned.m16n8k16.row.col.f32.f16.f16.f32 "
        "{%0,%1,%2,%3}, {%4,%5,%6,%7}, {%8,%9}, {%0,%1,%2,%3};"
        : "+f"(c[0]), "+f"(c[1]), "+f"(c[2]), "+f"(c[3])
        : "r"(a[0]), "r"(a[1]), "r"(a[2]), "r"(a[3]), "r"(b[0]), "r"(b[1]));
}

// ---------------------------------------------------------------------------
// Split-fp16 tensor-core GEMM: C[M,N] = alpha * A[M,K] @ B[N,K]^T
// TERMS=3: (Ah+Al)·Bh + Ah·Bl.  TERMS=2: (Ah+Al)·Bh.
// MODE 0: fp32 C.  MODE 1: fp16 hi/lo C pair.
// STATS 1: also emit per-CTA row softmax partials (max, sum-exp) to pm/ps.
// ---------------------------------------------------------------------------
#define LDT_B 80
#define TILE_B (128 * LDT_B)
#define STAGE_B (4 * TILE_B)
#define SMEMSZ (2 * STAGE_B)

template <int MODE, int TERMS, int STATS>
__global__ void __launch_bounds__(256) gemm_mma(
    const __half* __restrict__ Ah, const __half* __restrict__ Al,
    const __half* __restrict__ Bh, const __half* __restrict__ Bl,
    float* __restrict__ Cf, __half* __restrict__ Ch, __half* __restrict__ Cl,
    float* __restrict__ pm, float* __restrict__ ps,
    int K, int lda, int ldb, int ldc, float alpha,
    size_t sA, size_t sB, size_t sC)
{
    extern __shared__ char sm[];
    const uint32_t smb = s2u(sm);
    __shared__ float srm[STATS ? 128 : 1][4];
    __shared__ float srs[STATS ? 128 : 1][4];

    const int tid = threadIdx.x;
    const int wid = tid >> 5;
    const int lane = tid & 31;
    const int warp_m = wid & 1;
    const int warp_n = wid >> 1;

    Ah += blockIdx.z * sA; Al += blockIdx.z * sA;
    Bh += blockIdx.z * sB; Bl += blockIdx.z * sB;
    const size_t cOff = blockIdx.z * sC;

    const int bm = blockIdx.y * 128;
    const int bn = blockIdx.x * 128;

    const int c_row = tid >> 2;
    const int c_seg = tid & 3;

    const uint32_t aoff = (uint32_t)(((lane & 7) + ((lane >> 3) & 1) * 8) * LDT_B + (lane >> 4) * 16);
    const uint32_t boff = (uint32_t)(((lane >> 4) * 8 + (lane & 7)) * LDT_B + ((lane >> 3) & 1) * 16);

    float acc[4][4][4];
#pragma unroll
    for (int i = 0; i < 4; i++)
#pragma unroll
        for (int j = 0; j < 4; j++)
#pragma unroll
            for (int q = 0; q < 4; q++) acc[i][j][q] = 0.0f;

    const int nch = K >> 5;

    auto load_chunk = [&](int stage, int kb) {
        const uint32_t sb = smb + stage * STAGE_B;
#pragma unroll
        for (int s = 0; s < 2; s++) {
            const int row = c_row + s * 64;
            const uint32_t so = (uint32_t)(row * LDT_B + c_seg * 16);
            const size_t go = (size_t)row * lda + kb + c_seg * 8;
            cpa16(sb + so,              Ah + (size_t)bm * lda + go);
            cpa16(sb + TILE_B + so,     Al + (size_t)bm * lda + go);
            const size_t gob = (size_t)row * ldb + kb + c_seg * 8;
            cpa16(sb + 2 * TILE_B + so, Bh + (size_t)bn * ldb + gob);
            if constexpr (TERMS == 3)
                cpa16(sb + 3 * TILE_B + so, Bl + (size_t)bn * ldb + gob);
        }
        cpcommit();
    };

    load_chunk(0, 0);

    for (int c = 0; c < nch; c++) {
        if (c + 1 < nch) { load_chunk((c + 1) & 1, (c + 1) << 5); cpwait<1>(); }
        else             { cpwait<0>(); }
        __syncthreads();

        const uint32_t sb = smb + (c & 1) * STAGE_B;
        const uint32_t aH = sb + (uint32_t)(warp_m * 64) * LDT_B;
        const uint32_t aL = aH + TILE_B;
        const uint32_t bH = sb + 2 * TILE_B + (uint32_t)(warp_n * 32) * LDT_B;
        const uint32_t bL = bH + TILE_B;

#pragma unroll
        for (int ks = 0; ks < 2; ks++) {
            const uint32_t kb2 = ks * 32;
            uint32_t A[4][4], B[4][2];
#pragma unroll
            for (int mt = 0; mt < 4; mt++)
                ldm4(A[mt][0], A[mt][1], A[mt][2], A[mt][3],
                     aH + (uint32_t)(mt * 16) * LDT_B + aoff + kb2);
#pragma unroll
            for (int p = 0; p < 2; p++) {
                uint32_t r0, r1, r2, r3;
                ldm4(r0, r1, r2, r3, bH + (uint32_t)(p * 16) * LDT_B + boff + kb2);
                B[p * 2][0] = r0; B[p * 2][1] = r1;
                B[p * 2 + 1][0] = r2; B[p * 2 + 1][1] = r3;
            }
#pragma unroll
            for (int mt = 0; mt < 4; mt++)
#pragma unroll
                for (int nt = 0; nt < 4; nt++)
                    mma16816(acc[mt][nt], A[mt], B[nt]);

            if constexpr (TERMS == 3) {
                uint32_t BL[4][2];
#pragma unroll
                for (int p = 0; p < 2; p++) {
                    uint32_t r0, r1, r2, r3;
                    ldm4(r0, r1, r2, r3, bL + (uint32_t)(p * 16) * LDT_B + boff + kb2);
                    BL[p * 2][0] = r0; BL[p * 2][1] = r1;
                    BL[p * 2 + 1][0] = r2; BL[p * 2 + 1][1] = r3;
                }
#pragma unroll
                for (int mt = 0; mt < 4; mt++)
#pragma unroll
                    for (int nt = 0; nt < 4; nt++)
                        mma16816(acc[mt][nt], A[mt], BL[nt]);
            }
#pragma unroll
            for (int mt = 0; mt < 4; mt++)
                ldm4(A[mt][0], A[mt][1], A[mt][2], A[mt][3],
                     aL + (uint32_t)(mt * 16) * LDT_B + aoff + kb2);
#pragma unroll
            for (int mt = 0; mt < 4; mt++)
#pragma unroll
                for (int nt = 0; nt < 4; nt++)
                    mma16816(acc[mt][nt], A[mt], B[nt]);
        }
        __syncthreads();
    }

    const int g = lane >> 2;
    const int tq = lane & 3;
#pragma unroll
    for (int mt = 0; mt < 4; mt++) {
        const int row0 = bm + warp_m * 64 + mt * 16 + g;
        float v0s[4], v1s[4], v2s[4], v3s[4];
#pragma unroll
        for (int nt = 0; nt < 4; nt++) {
            const int col = bn + warp_n * 32 + nt * 8 + tq * 2;
            const float v0 = acc[mt][nt][0] * alpha;
            const float v1 = acc[mt][nt][1] * alpha;
            const float v2 = acc[mt][nt][2] * alpha;
            const float v3 = acc[mt][nt][3] * alpha;
            v0s[nt] = v0; v1s[nt] = v1; v2s[nt] = v2; v3s[nt] = v3;
            if (MODE == 0) {
                *reinterpret_cast<float2*>(Cf + cOff + (size_t)row0 * ldc + col) = make_float2(v0, v1);
                *reinterpret_cast<float2*>(Cf + cOff + (size_t)(row0 + 8) * ldc + col) = make_float2(v2, v3);
            } else {
                const __half h0 = __float2half_rn(v0), h1 = __float2half_rn(v1);
                const __half h2 = __float2half_rn(v2), h3 = __float2half_rn(v3);
                const __half l0 = __float2half_rn(v0 - __half2float(h0));
                const __half l1 = __float2half_rn(v1 - __half2float(h1));
                const __half l2 = __float2half_rn(v2 - __half2float(h2));
                const __half l3 = __float2half_rn(v3 - __half2float(h3));
                *reinterpret_cast<__half2*>(Ch + cOff + (size_t)row0 * ldc + col) = __halves2half2(h0, h1);
                *reinterpret_cast<__half2*>(Ch + cOff + (size_t)(row0 + 8) * ldc + col) = __halves2half2(h2, h3);
                *reinterpret_cast<__half2*>(Cl + cOff + (size_t)row0 * ldc + col) = __halves2half2(l0, l1);
                *reinterpret_cast<__half2*>(Cl + cOff + (size_t)(row0 + 8) * ldc + col) = __halves2half2(l2, l3);
            }
        }
        if constexpr (STATS) {
            // per-thread partial over 8 cols for row0 and row0+8
            float m0 = -1e30f, m1 = -1e30f;
#pragma unroll
            for (int nt = 0; nt < 4; nt++) {
                m0 = fmaxf(m0, fmaxf(v0s[nt], v1s[nt]));
                m1 = fmaxf(m1, fmaxf(v2s[nt], v3s[nt]));
            }
            float s0 = 0.0f, s1 = 0.0f;
#pragma unroll
            for (int nt = 0; nt < 4; nt++) {
                s0 += __expf(v0s[nt] - m0) + __expf(v1s[nt] - m0);
                s1 += __expf(v2s[nt] - m1) + __expf(v3s[nt] - m1);
            }
            // combine across the 4 tq lanes sharing this row
#pragma unroll
            for (int o = 1; o <= 2; o <<= 1) {
                float om = __shfl_xor_sync(0xffffffffu, m0, o);
                float os = __shfl_xor_sync(0xffffffffu, s0, o);
                float nm = fmaxf(m0, om);
                s0 = s0 * __expf(m0 - nm) + os * __expf(om - nm);
                m0 = nm;
                om = __shfl_xor_sync(0xffffffffu, m1, o);
                os = __shfl_xor_sync(0xffffffffu, s1, o);
                nm = fmaxf(m1, om);
                s1 = s1 * __expf(m1 - nm) + os * __expf(om - nm);
                m1 = nm;
            }
            if (tq == 0) {
                const int rl = warp_m * 64 + mt * 16 + g;
                srm[rl][warp_n] = m0; srs[rl][warp_n] = s0;
                srm[rl + 8][warp_n] = m1; srs[rl + 8][warp_n] = s1;
            }
        }
    }
    if constexpr (STATS) {
        __syncthreads();
        if (tid < 128) {
            float m = srm[tid][0], s = srs[tid][0];
#pragma unroll
            for (int w = 1; w < 4; w++) {
                const float om = srm[tid][w], os = srs[tid][w];
                const float nm = fmaxf(m, om);
                s = s * __expf(m - nm) + os * __expf(om - nm);
                m = nm;
            }
            const size_t idx = ((size_t)blockIdx.z * SEQ + bm + tid) * NBX + blockIdx.x;
            pm[idx] = m; ps[idx] = s;
        }
    }
}

// ---------------------------------------------------------------------------
// Combine per-CTA partials (NBX=32 per row) into final (max, 1/sum)
// ---------------------------------------------------------------------------
__global__ void __launch_bounds__(256) combine_stats(const float* __restrict__ pm,
                                                     const float* __restrict__ ps,
                                                     float* __restrict__ stats)
{
    const int row = blockIdx.x * 8 + (threadIdx.x >> 5);
    const int lane = threadIdx.x & 31;
    float m = pm[(size_t)row * NBX + lane];
    float s = ps[(size_t)row * NBX + lane];
#pragma unroll
    for (int o = 16; o; o >>= 1) {
        const float om = __shfl_xor_sync(0xffffffffu, m, o);
        const float os = __shfl_xor_sync(0xffffffffu, s, o);
        const float nm = fmaxf(m, om);
        s = s * __expf(m - nm) + os * __expf(om - nm);
        m = nm;
    }
    if (lane == 0) {
        stats[row] = m;
        stats[NROWS + row] = 1.0f / s;
    }
}

// ---------------------------------------------------------------------------
// Fused softmax-normalize + PV GEMM (unchanged from round 6)
// ---------------------------------------------------------------------------
#define PV_TILE (128 * LDT_B)
#define PV_SMEM (6 * PV_TILE)

__global__ void __launch_bounds__(256) pv_fused(
    float* __restrict__ attn, const float* __restrict__ stats,
    const __half* __restrict__ vth, const __half* __restrict__ vtl,
    __half* __restrict__ yh, __half* __restrict__ yl)
{
    extern __shared__ char sm[];
    const uint32_t smb = s2u(sm);
    __shared__ float sm_m[128], sm_inv[128];

    const int tid = threadIdx.x;
    const int wid = tid >> 5, lane = tid & 31;
    const int warp_m = wid & 1, warp_n = wid >> 1;
    const int z = blockIdx.z;
    const int bm = blockIdx.y * 128;

    float* ab = attn + (size_t)z * SEQ * SEQ + (size_t)bm * SEQ;
    const __half* vhb = vth + (size_t)(z * DK) * SEQ;
    const __half* vlb = vtl + (size_t)(z * DK) * SEQ;

    const int grow = z * SEQ + bm;
    if (tid < 128) {
        sm_m[tid] = stats[grow + tid];
        sm_inv[tid] = stats[NROWS + grow + tid];
    }
    __syncthreads();

    float4 pre[4];
    auto ldA = [&](int kb) {
#pragma unroll
        for (int i = 0; i < 4; i++) {
            const int idx = tid + i * 256;
            pre[i] = *reinterpret_cast<const float4*>(
                ab + (size_t)(idx >> 3) * SEQ + kb + (idx & 7) * 4);
        }
    };
    auto expsts = [&](int kb, int st) {
        const uint32_t as = smb + st * PV_TILE;
#pragma unroll
        for (int i = 0; i < 4; i++) {
            const int idx = tid + i * 256;
            const int r = idx >> 3, sg = idx & 7;
            const float m = sm_m[r], inv = sm_inv[r];
            float4 p;
            p.x = __expf(pre[i].x - m) * inv;
            p.y = __expf(pre[i].y - m) * inv;
            p.z = __expf(pre[i].z - m) * inv;
            p.w = __expf(pre[i].w - m) * inv;
            *reinterpret_cast<float4*>(ab + (size_t)r * SEQ + kb + sg * 4) = p;
            __half2 h01 = __floats2half2_rn(p.x, p.y);
            __half2 h23 = __floats2half2_rn(p.z, p.w);
            asm volatile("st.shared.v2.b32 [%0], {%1, %2};"
                         :: "r"(as + (uint32_t)(r * LDT_B + sg * 8)),
                            "r"(*reinterpret_cast<uint32_t*>(&h01)),
                            "r"(*reinterpret_cast<uint32_t*>(&h23)));
        }
    };
    auto ldV = [&](int kb, int st) {
        const uint32_t vs = smb + 2 * PV_TILE + st * 2 * PV_TILE;
#pragma unroll
        for (int i = 0; i < 2; i++) {
            const int idx = tid + i * 256;
            const int r = idx >> 2, sg = idx & 3;
            const uint32_t so = (uint32_t)(r * LDT_B + sg * 16);
            const size_t go = (size_t)r * SEQ + kb + sg * 8;
            cpa16(vs + so,           vhb + go);
            cpa16(vs + PV_TILE + so, vlb + go);
        }
        cpcommit();
    };

    const uint32_t aoff = (uint32_t)(((lane & 7) + ((lane >> 3) & 1) * 8) * LDT_B + (lane >> 4) * 16);
    const uint32_t boff = (uint32_t)(((lane >> 4) * 8 + (lane & 7)) * LDT_B + ((lane >> 3) & 1) * 16);

    float acc[4][4][4];
#pragma unroll
    for (int i = 0; i < 4; i++)
#pragma unroll
        for (int j = 0; j < 4; j++)
#pragma unroll
            for (int q = 0; q < 4; q++) acc[i][j][q] = 0.0f;

    ldA(0); ldV(0, 0);
    expsts(0, 0);

    const int nch = SEQ / 32;
    for (int c = 0; c < nch; c++) {
        if (c + 1 < nch) { ldA((c + 1) * 32); ldV((c + 1) * 32, (c + 1) & 1); cpwait<1>(); }
        else             { cpwait<0>(); }
        __syncthreads();

        const uint32_t as  = smb + (c & 1) * PV_TILE;
        const uint32_t vhs = smb + 2 * PV_TILE + (c & 1) * 2 * PV_TILE;
        const uint32_t vls = vhs + PV_TILE;

#pragma unroll
        for (int ks = 0; ks < 2; ks++) {
            const uint32_t kb2 = ks * 32;
            uint32_t A[4][4], B[4][2], BL[4][2];
#pragma unroll
            for (int mt = 0; mt < 4; mt++)
                ldm4(A[mt][0], A[mt][1], A[mt][2], A[mt][3],
                     as + (uint32_t)((warp_m * 64 + mt * 16) * LDT_B) + aoff + kb2);
#pragma unroll
            for (int p = 0; p < 2; p++) {
                uint32_t r0, r1, r2, r3;
                ldm4(r0, r1, r2, r3, vhs + (uint32_t)((warp_n * 32 + p * 16) * LDT_B) + boff + kb2);
                B[p * 2][0] = r0; B[p * 2][1] = r1;
                B[p * 2 + 1][0] = r2; B[p * 2 + 1][1] = r3;
            }
#pragma unroll
            for (int p = 0; p < 2; p++) {
                uint32_t r0, r1, r2, r3;
                ldm4(r0, r1, r2, r3, vls + (uint32_t)((warp_n * 32 + p * 16) * LDT_B) + boff + kb2);
                BL[p * 2][0] = r0; BL[p * 2][1] = r1;
                BL[p * 2 + 1][0] = r2; BL[p * 2 + 1][1] = r3;
            }
#pragma unroll
            for (int mt = 0; mt < 4; mt++)
#pragma unroll
                for (int nt = 0; nt < 4; nt++)
                    mma16816(acc[mt][nt], A[mt], B[nt]);
#pragma unroll
            for (int mt = 0; mt < 4; mt++)
#pragma unroll
                for (int nt = 0; nt < 4; nt++)
                    mma16816(acc[mt][nt], A[mt], BL[nt]);
        }
        if (c + 1 < nch) expsts((c + 1) * 32, (c + 1) & 1);
        __syncthreads();
    }

    const int g = lane >> 2, tq = lane & 3;
#pragma unroll
    for (int mt = 0; mt < 4; mt++) {
        const int row0 = bm + warp_m * 64 + mt * 16 + g;
#pragma unroll
        for (int nt = 0; nt < 4; nt++) {
            const int col = z * DK + warp_n * 32 + nt * 8 + tq * 2;
            const float v0 = acc[mt][nt][0], v1 = acc[mt][nt][1];
            const float v2 = acc[mt][nt][2], v3 = acc[mt][nt][3];
            const __half h0 = __float2half_rn(v0), h1 = __float2half_rn(v1);
            const __half h2 = __float2half_rn(v2), h3 = __float2half_rn(v3);
            const __half l0 = __float2half_rn(v0 - __half2float(h0));
            const __half l1 = __float2half_rn(v1 - __half2float(h1));
            const __half l2 = __float2half_rn(v2 - __half2float(h2));
            const __half l3 = __float2half_rn(v3 - __half2float(h3));
            *reinterpret_cast<__half2*>(yh + (size_t)row0 * HID + col) = __halves2half2(h0, h1);
            *reinterpret_cast<__half2*>(yh + (size_t)(row0 + 8) * HID + col) = __halves2half2(h2, h3);
            *reinterpret_cast<__half2*>(yl + (size_t)row0 * HID + col) = __halves2half2(l0, l1);
            *reinterpret_cast<__half2*>(yl + (size_t)(row0 + 8) * HID + col) = __halves2half2(l2, l3);
        }
    }
}

// ---------------------------------------------------------------------------
// Prep kernels
// ---------------------------------------------------------------------------
__global__ void convert_split(const float* __restrict__ in,
                              __half* __restrict__ oh, __half* __restrict__ ol, int n4)
{
    const int i = blockIdx.x * blockDim.x + threadIdx.x;
    if (i >= n4) return;
    const float4 v = reinterpret_cast<const float4*>(in)[i];
    const __half h0 = __float2half_rn(v.x), h1 = __float2half_rn(v.y);
    const __half h2 = __float2half_rn(v.z), h3 = __float2half_rn(v.w);
    const __half l0 = __float2half_rn(v.x - __half2float(h0));
    const __half l1 = __float2half_rn(v.y - __half2float(h1));
    const __half l2 = __float2half_rn(v.z - __half2float(h2));
    const __half l3 = __float2half_rn(v.w - __half2float(h3));
    __half2 ha = __halves2half2(h0, h1), hb = __halves2half2(h2, h3);
    __half2 la = __halves2half2(l0, l1), lb = __halves2half2(l2, l3);
    uint2 uh, ul;
    uh.x = *reinterpret_cast<uint32_t*>(&ha); uh.y = *reinterpret_cast<uint32_t*>(&hb);
    ul.x = *reinterpret_cast<uint32_t*>(&la); ul.y = *reinterpret_cast<uint32_t*>(&lb);
    reinterpret_cast<uint2*>(oh)[i] = uh;
    reinterpret_cast<uint2*>(ol)[i] = ul;
}

__global__ void transpose_split(const float* __restrict__ in,
                                __half* __restrict__ oh, __half* __restrict__ ol, int R, int C)
{
    __shared__ float t[32][33];
    const int bc = blockIdx.x * 32, br = blockIdx.y * 32;
    const int x = threadIdx.x, y = threadIdx.y;
#pragma unroll
    for (int j = 0; j < 32; j += 8)
        t[y + j][x] = in[(size_t)(br + y + j) * C + bc + x];
    __syncthreads();
#pragma unroll
    for (int j = 0; j < 32; j += 8) {
        const float v = t[x][y + j];
        const __half h = __float2half_rn(v);
        const size_t o = (size_t)(bc + y + j) * R + br + x;
        oh[o] = h;
        ol[o] = __float2half_rn(v - __half2float(h));
    }
}

// ---------------------------------------------------------------------------
extern "C" void kernel_launch(void* const* d_in, const int* in_sizes, int n_in,
                              void* d_out, int out_size)
{
    const float* x  = (const float*)d_in[0];
    const float* Wq = (const float*)d_in[1];
    const float* Wk = (const float*)d_in[2];
    const float* Wv = (const float*)d_in[3];
    const float* Wo = (const float*)d_in[4];
    float* out = (float*)d_out;

    cudaFuncSetAttribute(gemm_mma<0, 2, 0>, cudaFuncAttributeMaxDynamicSharedMemorySize, SMEMSZ);
    cudaFuncSetAttribute(gemm_mma<1, 2, 0>, cudaFuncAttributeMaxDynamicSharedMemorySize, SMEMSZ);
    cudaFuncSetAttribute(gemm_mma<0, 3, 1>, cudaFuncAttributeMaxDynamicSharedMemorySize, SMEMSZ);
    cudaFuncSetAttribute(pv_fused, cudaFuncAttributeMaxDynamicSharedMemorySize, PV_SMEM);

    __half *xh, *xl, *wqth, *wqtl, *wkth, *wktl, *wvth, *wvtl, *woth, *wotl;
    __half *qh, *ql, *kh, *kl, *vth, *vtl, *yh, *yl;
    float *vf, *stats, *pm, *ps;
    cudaGetSymbolAddress((void**)&xh, g_xh);     cudaGetSymbolAddress((void**)&xl, g_xl);
    cudaGetSymbolAddress((void**)&wqth, g_wqth); cudaGetSymbolAddress((void**)&wqtl, g_wqtl);
    cudaGetSymbolAddress((void**)&wkth, g_wkth); cudaGetSymbolAddress((void**)&wktl, g_wktl);
    cudaGetSymbolAddress((void**)&wvth, g_wvth); cudaGetSymbolAddress((void**)&wvtl, g_wvtl);
    cudaGetSymbolAddress((void**)&woth, g_woth); cudaGetSymbolAddress((void**)&wotl, g_wotl);
    cudaGetSymbolAddress((void**)&qh, g_qh);     cudaGetSymbolAddress((void**)&ql, g_ql);
    cudaGetSymbolAddress((void**)&kh, g_kh);     cudaGetSymbolAddress((void**)&kl, g_kl);
    cudaGetSymbolAddress((void**)&vf, g_vf);
    cudaGetSymbolAddress((void**)&vth, g_vth);   cudaGetSymbolAddress((void**)&vtl, g_vtl);
    cudaGetSymbolAddress((void**)&yh, g_yh);     cudaGetSymbolAddress((void**)&yl, g_yl);
    cudaGetSymbolAddress((void**)&stats, g_stats);
    cudaGetSymbolAddress((void**)&pm, g_pm);     cudaGetSymbolAddress((void**)&ps, g_ps);

    const size_t ySz = (size_t)SEQ * FEAT;
    const size_t aSz = (size_t)NH * SEQ * SEQ;
    float* attn;
    if ((size_t)out_size >= ySz + aSz) attn = out + ySz;
    else cudaGetSymbolAddress((void**)&attn, g_attn_fb);

    // Prep: split x, transpose+split weights
    convert_split<<<(SEQ * FEAT / 4 + 255) / 256, 256>>>(x, xh, xl, SEQ * FEAT / 4);
    dim3 tb(32, 8);
    transpose_split<<<dim3(HID / 32, FEAT / 32), tb>>>(Wq, wqth, wqtl, FEAT, HID);
    transpose_split<<<dim3(HID / 32, FEAT / 32), tb>>>(Wk, wkth, wktl, FEAT, HID);
    transpose_split<<<dim3(HID / 32, FEAT / 32), tb>>>(Wv, wvth, wvtl, FEAT, HID);
    transpose_split<<<dim3(FEAT / 32, HID / 32), tb>>>(Wo, woth, wotl, HID, FEAT);

    // QKV projections: 2-term
    gemm_mma<1, 2, 0><<<dim3(HID / 128, SEQ / 128, 1), 256, SMEMSZ>>>(
        xh, xl, wqth, wqtl, nullptr, qh, ql, nullptr, nullptr,
        FEAT, FEAT, FEAT, HID, 1.0f, 0, 0, 0);
    gemm_mma<1, 2, 0><<<dim3(HID / 128, SEQ / 128, 1), 256, SMEMSZ>>>(
        xh, xl, wkth, wktl, nullptr, kh, kl, nullptr, nullptr,
        FEAT, FEAT, FEAT, HID, 1.0f, 0, 0, 0);
    gemm_mma<0, 2, 0><<<dim3(HID / 128, SEQ / 128, 1), 256, SMEMSZ>>>(
        xh, xl, wvth, wvtl, vf, nullptr, nullptr, nullptr, nullptr,
        FEAT, FEAT, FEAT, HID, 1.0f, 0, 0, 0);
    transpose_split<<<dim3(HID / 32, SEQ / 32), tb>>>(vf, vth, vtl, SEQ, HID);

    // Scores: 3-term, fp32 scaled scores + fused softmax partials
    const float alpha = 0.08838834764831845f; // 1/sqrt(128)
    gemm_mma<0, 3, 1><<<dim3(SEQ / 128, SEQ / 128, NH), 256, SMEMSZ>>>(
        qh, ql, kh, kl, attn, nullptr, nullptr, pm, ps,
        DK, HID, HID, SEQ, alpha,
        (size_t)DK, (size_t)DK, (size_t)SEQ * SEQ);

    // Combine partials into final (max, 1/sum)
    combine_stats<<<NROWS / 8, 256>>>(pm, ps, stats);

    // Fused normalize + PV
    pv_fused<<<dim3(1, SEQ / 128, NH), 256, PV_SMEM>>>(attn, stats, vth, vtl, yh, yl);

    // Output projection: 2-term
    gemm_mma<0, 2, 0><<<dim3(FEAT / 128, SEQ / 128, 1), 256, SMEMSZ>>>(
        yh, yl, woth, wotl, out, nullptr, nullptr, nullptr, nullptr,
        HID, HID, HID, FEAT, 1.0f, 0, 0, 0);
}

// round 8
// speedup vs baseline: 3.1475x; 1.1084x over previous
#include <cuda_runtime.h>
#include <cuda_fp16.h>
#include <cstdint>
#include <math.h>

#define SEQ 4096
#define FEAT 1024
#define HID 1024
#define NH 8
#define DK 128
#define NROWS (NH * SEQ)
#define NBX 32   // score col-blocks per row

// ---------------------------------------------------------------------------
// Device-global scratch (allocation-free per harness rules)
// ---------------------------------------------------------------------------
__device__ __half g_xh[(size_t)SEQ * FEAT], g_xl[(size_t)SEQ * FEAT];
__device__ __half g_wqth[(size_t)HID * FEAT], g_wqtl[(size_t)HID * FEAT];
__device__ __half g_wkth[(size_t)HID * FEAT], g_wktl[(size_t)HID * FEAT];
__device__ __half g_wvth[(size_t)HID * FEAT], g_wvtl[(size_t)HID * FEAT];
__device__ __half g_woth[(size_t)FEAT * HID], g_wotl[(size_t)FEAT * HID];
__device__ __half g_qh[(size_t)SEQ * HID], g_ql[(size_t)SEQ * HID];
__device__ __half g_kh[(size_t)SEQ * HID], g_kl[(size_t)SEQ * HID];
__device__ float  g_vf[(size_t)SEQ * HID];
__device__ __half g_vth[(size_t)HID * SEQ], g_vtl[(size_t)HID * SEQ];
__device__ __half g_yh[(size_t)SEQ * HID], g_yl[(size_t)SEQ * HID];
__device__ float  g_stats[2 * NROWS];
__device__ float  g_pm[(size_t)NROWS * NBX], g_ps[(size_t)NROWS * NBX];
__device__ float  g_attn_fb[(size_t)NH * SEQ * SEQ];

// ---------------------------------------------------------------------------
// PTX helpers (arch-agnostic: cp.async sm_80+, ldmatrix sm_75+, mma sm_80+)
// ---------------------------------------------------------------------------
__device__ __forceinline__ uint32_t s2u(const void* p) {
    uint32_t a;
    asm("{ .reg .u64 t; cvta.to.shared.u64 t, %1; cvt.u32.u64 %0, t; }" : "=r"(a) : "l"(p));
    return a;
}
__device__ __forceinline__ void cpa16(uint32_t d, const void* s) {
    asm volatile("cp.async.cg.shared.global [%0], [%1], 16;" :: "r"(d), "l"(s));
}
__device__ __forceinline__ void cpcommit() { asm volatile("cp.async.commit_group;"); }
template <int N>
__device__ __forceinline__ void cpwait() { asm volatile("cp.async.wait_group %0;" :: "n"(N)); }

__device__ __forceinline__ void ldm4(uint32_t& r0, uint32_t& r1, uint32_t& r2, uint32_t& r3, uint32_t a) {
    asm volatile("ldmatrix.sync.aligned.m8n8.x4.shared.b16 {%0,%1,%2,%3}, [%4];"
                 : "=r"(r0), "=r"(r1), "=r"(r2), "=r"(r3) : "r"(a));
}
__device__ __forceinline__ void mma16816(float* c, const uint32_t* a, const uint32_t* b) {
    asm volatile(
        "mma.sync.aligned.m16n8k16.row.col.f32.f16.f16.f32 "
        "{%0,%1,%2,%3}, {%4,%5,%6,%7}, {%8,%9}, {%0,%1,%2,%3};"
        : "+f"(c[0]), "+f"(c[1]), "+f"(c[2]), "+f"(c[3])
        : "r"(a[0]), "r"(a[1]), "r"(a[2]), "r"(a[3]), "r"(b[0]), "r"(b[1]));
}

// ---------------------------------------------------------------------------
// Split-fp16 tensor-core GEMM: C[M,N] = alpha * A[M,K] @ B[N,K]^T
// TERMS=3: (Ah+Al)·Bh + Ah·Bl.  TERMS=2: (Ah+Al)·Bh.
// MODE 0: fp32 C.  MODE 1: fp16 hi/lo C pair.
// STATS 1: also emit per-CTA row softmax partials (max, sum-exp) to pm/ps.
// ---------------------------------------------------------------------------
#define LDT_B 80
#define TILE_B (128 * LDT_B)
#define STAGE_B (4 * TILE_B)
#define SMEMSZ (2 * STAGE_B)

template <int MODE, int TERMS, int STATS>
__global__ void __launch_bounds__(256) gemm_mma(
    const __half* __restrict__ Ah, const __half* __restrict__ Al,
    const __half* __restrict__ Bh, const __half* __restrict__ Bl,
    float* __restrict__ Cf, __half* __restrict__ Ch, __half* __restrict__ Cl,
    float* __restrict__ pm, float* __restrict__ ps,
    int K, int lda, int ldb, int ldc, float alpha,
    size_t sA, size_t sB, size_t sC)
{
    extern __shared__ char sm[];
    const uint32_t smb = s2u(sm);
    __shared__ float srm[STATS ? 128 : 1][4];
    __shared__ float srs[STATS ? 128 : 1][4];

    const int tid = threadIdx.x;
    const int wid = tid >> 5;
    const int lane = tid & 31;
    const int warp_m = wid & 1;
    const int warp_n = wid >> 1;

    Ah += blockIdx.z * sA; Al += blockIdx.z * sA;
    Bh += blockIdx.z * sB; Bl += blockIdx.z * sB;
    const size_t cOff = blockIdx.z * sC;

    const int bm = blockIdx.y * 128;
    const int bn = blockIdx.x * 128;

    const int c_row = tid >> 2;
    const int c_seg = tid & 3;

    const uint32_t aoff = (uint32_t)(((lane & 7) + ((lane >> 3) & 1) * 8) * LDT_B + (lane >> 4) * 16);
    const uint32_t boff = (uint32_t)(((lane >> 4) * 8 + (lane & 7)) * LDT_B + ((lane >> 3) & 1) * 16);

    float acc[4][4][4];
#pragma unroll
    for (int i = 0; i < 4; i++)
#pragma unroll
        for (int j = 0; j < 4; j++)
#pragma unroll
            for (int q = 0; q < 4; q++) acc[i][j][q] = 0.0f;

    const int nch = K >> 5;

    auto load_chunk = [&](int stage, int kb) {
        const uint32_t sb = smb + stage * STAGE_B;
#pragma unroll
        for (int s = 0; s < 2; s++) {
            const int row = c_row + s * 64;
            const uint32_t so = (uint32_t)(row * LDT_B + c_seg * 16);
            const size_t go = (size_t)row * lda + kb + c_seg * 8;
            cpa16(sb + so,              Ah + (size_t)bm * lda + go);
            cpa16(sb + TILE_B + so,     Al + (size_t)bm * lda + go);
            const size_t gob = (size_t)row * ldb + kb + c_seg * 8;
            cpa16(sb + 2 * TILE_B + so, Bh + (size_t)bn * ldb + gob);
            if constexpr (TERMS == 3)
                cpa16(sb + 3 * TILE_B + so, Bl + (size_t)bn * ldb + gob);
        }
        cpcommit();
    };

    load_chunk(0, 0);

    for (int c = 0; c < nch; c++) {
        if (c + 1 < nch) { load_chunk((c + 1) & 1, (c + 1) << 5); cpwait<1>(); }
        else             { cpwait<0>(); }
        __syncthreads();

        const uint32_t sb = smb + (c & 1) * STAGE_B;
        const uint32_t aH = sb + (uint32_t)(warp_m * 64) * LDT_B;
        const uint32_t aL = aH + TILE_B;
        const uint32_t bH = sb + 2 * TILE_B + (uint32_t)(warp_n * 32) * LDT_B;
        const uint32_t bL = bH + TILE_B;

#pragma unroll
        for (int ks = 0; ks < 2; ks++) {
            const uint32_t kb2 = ks * 32;
            uint32_t A[4][4], B[4][2];
#pragma unroll
            for (int mt = 0; mt < 4; mt++)
                ldm4(A[mt][0], A[mt][1], A[mt][2], A[mt][3],
                     aH + (uint32_t)(mt * 16) * LDT_B + aoff + kb2);
#pragma unroll
            for (int p = 0; p < 2; p++) {
                uint32_t r0, r1, r2, r3;
                ldm4(r0, r1, r2, r3, bH + (uint32_t)(p * 16) * LDT_B + boff + kb2);
                B[p * 2][0] = r0; B[p * 2][1] = r1;
                B[p * 2 + 1][0] = r2; B[p * 2 + 1][1] = r3;
            }
#pragma unroll
            for (int mt = 0; mt < 4; mt++)
#pragma unroll
                for (int nt = 0; nt < 4; nt++)
                    mma16816(acc[mt][nt], A[mt], B[nt]);

            if constexpr (TERMS == 3) {
                uint32_t BL[4][2];
#pragma unroll
                for (int p = 0; p < 2; p++) {
                    uint32_t r0, r1, r2, r3;
                    ldm4(r0, r1, r2, r3, bL + (uint32_t)(p * 16) * LDT_B + boff + kb2);
                    BL[p * 2][0] = r0; BL[p * 2][1] = r1;
                    BL[p * 2 + 1][0] = r2; BL[p * 2 + 1][1] = r3;
                }
#pragma unroll
                for (int mt = 0; mt < 4; mt++)
#pragma unroll
                    for (int nt = 0; nt < 4; nt++)
                        mma16816(acc[mt][nt], A[mt], BL[nt]);
            }
#pragma unroll
            for (int mt = 0; mt < 4; mt++)
                ldm4(A[mt][0], A[mt][1], A[mt][2], A[mt][3],
                     aL + (uint32_t)(mt * 16) * LDT_B + aoff + kb2);
#pragma unroll
            for (int mt = 0; mt < 4; mt++)
#pragma unroll
                for (int nt = 0; nt < 4; nt++)
                    mma16816(acc[mt][nt], A[mt], B[nt]);
        }
        __syncthreads();
    }

    const int g = lane >> 2;
    const int tq = lane & 3;
#pragma unroll
    for (int mt = 0; mt < 4; mt++) {
        const int row0 = bm + warp_m * 64 + mt * 16 + g;
        float v0s[4], v1s[4], v2s[4], v3s[4];
#pragma unroll
        for (int nt = 0; nt < 4; nt++) {
            const int col = bn + warp_n * 32 + nt * 8 + tq * 2;
            const float v0 = acc[mt][nt][0] * alpha;
            const float v1 = acc[mt][nt][1] * alpha;
            const float v2 = acc[mt][nt][2] * alpha;
            const float v3 = acc[mt][nt][3] * alpha;
            v0s[nt] = v0; v1s[nt] = v1; v2s[nt] = v2; v3s[nt] = v3;
            if (MODE == 0) {
                *reinterpret_cast<float2*>(Cf + cOff + (size_t)row0 * ldc + col) = make_float2(v0, v1);
                *reinterpret_cast<float2*>(Cf + cOff + (size_t)(row0 + 8) * ldc + col) = make_float2(v2, v3);
            } else {
                const __half h0 = __float2half_rn(v0), h1 = __float2half_rn(v1);
                const __half h2 = __float2half_rn(v2), h3 = __float2half_rn(v3);
                const __half l0 = __float2half_rn(v0 - __half2float(h0));
                const __half l1 = __float2half_rn(v1 - __half2float(h1));
                const __half l2 = __float2half_rn(v2 - __half2float(h2));
                const __half l3 = __float2half_rn(v3 - __half2float(h3));
                *reinterpret_cast<__half2*>(Ch + cOff + (size_t)row0 * ldc + col) = __halves2half2(h0, h1);
                *reinterpret_cast<__half2*>(Ch + cOff + (size_t)(row0 + 8) * ldc + col) = __halves2half2(h2, h3);
                *reinterpret_cast<__half2*>(Cl + cOff + (size_t)row0 * ldc + col) = __halves2half2(l0, l1);
                *reinterpret_cast<__half2*>(Cl + cOff + (size_t)(row0 + 8) * ldc + col) = __halves2half2(l2, l3);
            }
        }
        if constexpr (STATS) {
            float m0 = -1e30f, m1 = -1e30f;
#pragma unroll
            for (int nt = 0; nt < 4; nt++) {
                m0 = fmaxf(m0, fmaxf(v0s[nt], v1s[nt]));
                m1 = fmaxf(m1, fmaxf(v2s[nt], v3s[nt]));
            }
            float s0 = 0.0f, s1 = 0.0f;
#pragma unroll
            for (int nt = 0; nt < 4; nt++) {
                s0 += __expf(v0s[nt] - m0) + __expf(v1s[nt] - m0);
                s1 += __expf(v2s[nt] - m1) + __expf(v3s[nt] - m1);
            }
#pragma unroll
            for (int o = 1; o <= 2; o <<= 1) {
                float om = __shfl_xor_sync(0xffffffffu, m0, o);
                float os = __shfl_xor_sync(0xffffffffu, s0, o);
                float nm = fmaxf(m0, om);
                s0 = s0 * __expf(m0 - nm) + os * __expf(om - nm);
                m0 = nm;
                om = __shfl_xor_sync(0xffffffffu, m1, o);
                os = __shfl_xor_sync(0xffffffffu, s1, o);
                nm = fmaxf(m1, om);
                s1 = s1 * __expf(m1 - nm) + os * __expf(om - nm);
                m1 = nm;
            }
            if (tq == 0) {
                const int rl = warp_m * 64 + mt * 16 + g;
                srm[rl][warp_n] = m0; srs[rl][warp_n] = s0;
                srm[rl + 8][warp_n] = m1; srs[rl + 8][warp_n] = s1;
            }
        }
    }
    if constexpr (STATS) {
        __syncthreads();
        if (tid < 128) {
            float m = srm[tid][0], s = srs[tid][0];
#pragma unroll
            for (int w = 1; w < 4; w++) {
                const float om = srm[tid][w], os = srs[tid][w];
                const float nm = fmaxf(m, om);
                s = s * __expf(m - nm) + os * __expf(om - nm);
                m = nm;
            }
            const size_t idx = ((size_t)blockIdx.z * SEQ + bm + tid) * NBX + blockIdx.x;
            pm[idx] = m; ps[idx] = s;
        }
    }
}

// ---------------------------------------------------------------------------
// Combine per-CTA partials (NBX=32 per row) into final (max, 1/sum)
// ---------------------------------------------------------------------------
__global__ void __launch_bounds__(256) combine_stats(const float* __restrict__ pm,
                                                     const float* __restrict__ ps,
                                                     float* __restrict__ stats)
{
    const int row = blockIdx.x * 8 + (threadIdx.x >> 5);
    const int lane = threadIdx.x & 31;
    float m = pm[(size_t)row * NBX + lane];
    float s = ps[(size_t)row * NBX + lane];
#pragma unroll
    for (int o = 16; o; o >>= 1) {
        const float om = __shfl_xor_sync(0xffffffffu, m, o);
        const float os = __shfl_xor_sync(0xffffffffu, s, o);
        const float nm = fmaxf(m, om);
        s = s * __expf(m - nm) + os * __expf(om - nm);
        m = nm;
    }
    if (lane == 0) {
        stats[row] = m;
        stats[NROWS + row] = 1.0f / s;
    }
}

// ---------------------------------------------------------------------------
// Fused softmax-normalize + PV GEMM, 1-term (V single fp16).
// ---------------------------------------------------------------------------
#define PV_TILE (128 * LDT_B)
#define PV_SMEM (4 * PV_TILE)

__global__ void __launch_bounds__(256) pv_fused(
    float* __restrict__ attn, const float* __restrict__ stats,
    const __half* __restrict__ vth,
    __half* __restrict__ yh, __half* __restrict__ yl)
{
    extern __shared__ char sm[];
    const uint32_t smb = s2u(sm);
    __shared__ float sm_m[128], sm_inv[128];

    const int tid = threadIdx.x;
    const int wid = tid >> 5, lane = tid & 31;
    const int warp_m = wid & 1, warp_n = wid >> 1;
    const int z = blockIdx.z;
    const int bm = blockIdx.y * 128;

    float* ab = attn + (size_t)z * SEQ * SEQ + (size_t)bm * SEQ;
    const __half* vhb = vth + (size_t)(z * DK) * SEQ;

    const int grow = z * SEQ + bm;
    if (tid < 128) {
        sm_m[tid] = stats[grow + tid];
        sm_inv[tid] = stats[NROWS + grow + tid];
    }
    __syncthreads();

    float4 pre[4];
    auto ldA = [&](int kb) {
#pragma unroll
        for (int i = 0; i < 4; i++) {
            const int idx = tid + i * 256;
            pre[i] = *reinterpret_cast<const float4*>(
                ab + (size_t)(idx >> 3) * SEQ + kb + (idx & 7) * 4);
        }
    };
    auto expsts = [&](int kb, int st) {
        const uint32_t as = smb + st * PV_TILE;
#pragma unroll
        for (int i = 0; i < 4; i++) {
            const int idx = tid + i * 256;
            const int r = idx >> 3, sg = idx & 7;
            const float m = sm_m[r], inv = sm_inv[r];
            float4 p;
            p.x = __expf(pre[i].x - m) * inv;
            p.y = __expf(pre[i].y - m) * inv;
            p.z = __expf(pre[i].z - m) * inv;
            p.w = __expf(pre[i].w - m) * inv;
            *reinterpret_cast<float4*>(ab + (size_t)r * SEQ + kb + sg * 4) = p;
            __half2 h01 = __floats2half2_rn(p.x, p.y);
            __half2 h23 = __floats2half2_rn(p.z, p.w);
            asm volatile("st.shared.v2.b32 [%0], {%1, %2};"
                         :: "r"(as + (uint32_t)(r * LDT_B + sg * 8)),
                            "r"(*reinterpret_cast<uint32_t*>(&h01)),
                            "r"(*reinterpret_cast<uint32_t*>(&h23)));
        }
    };
    auto ldV = [&](int kb, int st) {
        const uint32_t vs = smb + 2 * PV_TILE + st * PV_TILE;
#pragma unroll
        for (int i = 0; i < 2; i++) {
            const int idx = tid + i * 256;
            const int r = idx >> 2, sg = idx & 3;
            cpa16(vs + (uint32_t)(r * LDT_B + sg * 16),
                  vhb + (size_t)r * SEQ + kb + sg * 8);
        }
        cpcommit();
    };

    const uint32_t aoff = (uint32_t)(((lane & 7) + ((lane >> 3) & 1) * 8) * LDT_B + (lane >> 4) * 16);
    const uint32_t boff = (uint32_t)(((lane >> 4) * 8 + (lane & 7)) * LDT_B + ((lane >> 3) & 1) * 16);

    float acc[4][4][4];
#pragma unroll
    for (int i = 0; i < 4; i++)
#pragma unroll
        for (int j = 0; j < 4; j++)
#pragma unroll
            for (int q = 0; q < 4; q++) acc[i][j][q] = 0.0f;

    ldA(0); ldV(0, 0);
    expsts(0, 0);

    const int nch = SEQ / 32;
    for (int c = 0; c < nch; c++) {
        if (c + 1 < nch) { ldA((c + 1) * 32); ldV((c + 1) * 32, (c + 1) & 1); cpwait<1>(); }
        else             { cpwait<0>(); }
        __syncthreads();

        const uint32_t as  = smb + (c & 1) * PV_TILE;
        const uint32_t vhs = smb + 2 * PV_TILE + (c & 1) * PV_TILE;

#pragma unroll
        for (int ks = 0; ks < 2; ks++) {
            const uint32_t kb2 = ks * 32;
            uint32_t A[4][4], B[4][2];
#pragma unroll
            for (int mt = 0; mt < 4; mt++)
                ldm4(A[mt][0], A[mt][1], A[mt][2], A[mt][3],
                     as + (uint32_t)((warp_m * 64 + mt * 16) * LDT_B) + aoff + kb2);
#pragma unroll
            for (int p = 0; p < 2; p++) {
                uint32_t r0, r1, r2, r3;
                ldm4(r0, r1, r2, r3, vhs + (uint32_t)((warp_n * 32 + p * 16) * LDT_B) + boff + kb2);
                B[p * 2][0] = r0; B[p * 2][1] = r1;
                B[p * 2 + 1][0] = r2; B[p * 2 + 1][1] = r3;
            }
#pragma unroll
            for (int mt = 0; mt < 4; mt++)
#pragma unroll
                for (int nt = 0; nt < 4; nt++)
                    mma16816(acc[mt][nt], A[mt], B[nt]);
        }
        if (c + 1 < nch) expsts((c + 1) * 32, (c + 1) & 1);
        __syncthreads();
    }

    const int g = lane >> 2, tq = lane & 3;
#pragma unroll
    for (int mt = 0; mt < 4; mt++) {
        const int row0 = bm + warp_m * 64 + mt * 16 + g;
#pragma unroll
        for (int nt = 0; nt < 4; nt++) {
            const int col = z * DK + warp_n * 32 + nt * 8 + tq * 2;
            const float v0 = acc[mt][nt][0], v1 = acc[mt][nt][1];
            const float v2 = acc[mt][nt][2], v3 = acc[mt][nt][3];
            const __half h0 = __float2half_rn(v0), h1 = __float2half_rn(v1);
            const __half h2 = __float2half_rn(v2), h3 = __float2half_rn(v3);
            const __half l0 = __float2half_rn(v0 - __half2float(h0));
            const __half l1 = __float2half_rn(v1 - __half2float(h1));
            const __half l2 = __float2half_rn(v2 - __half2float(h2));
            const __half l3 = __float2half_rn(v3 - __half2float(h3));
            *reinterpret_cast<__half2*>(yh + (size_t)row0 * HID + col) = __halves2half2(h0, h1);
            *reinterpret_cast<__half2*>(yh + (size_t)(row0 + 8) * HID + col) = __halves2half2(h2, h3);
            *reinterpret_cast<__half2*>(yl + (size_t)row0 * HID + col) = __halves2half2(l0, l1);
            *reinterpret_cast<__half2*>(yl + (size_t)(row0 + 8) * HID + col) = __halves2half2(l2, l3);
        }
    }
}

// ---------------------------------------------------------------------------
// Prep kernels
// ---------------------------------------------------------------------------
__global__ void convert_split(const float* __restrict__ in,
                              __half* __restrict__ oh, __half* __restrict__ ol, int n4)
{
    const int i = blockIdx.x * blockDim.x + threadIdx.x;
    if (i >= n4) return;
    const float4 v = reinterpret_cast<const float4*>(in)[i];
    const __half h0 = __float2half_rn(v.x), h1 = __float2half_rn(v.y);
    const __half h2 = __float2half_rn(v.z), h3 = __float2half_rn(v.w);
    const __half l0 = __float2half_rn(v.x - __half2float(h0));
    const __half l1 = __float2half_rn(v.y - __half2float(h1));
    const __half l2 = __float2half_rn(v.z - __half2float(h2));
    const __half l3 = __float2half_rn(v.w - __half2float(h3));
    __half2 ha = __halves2half2(h0, h1), hb = __halves2half2(h2, h3);
    __half2 la = __halves2half2(l0, l1), lb = __halves2half2(l2, l3);
    uint2 uh, ul;
    uh.x = *reinterpret_cast<uint32_t*>(&ha); uh.y = *reinterpret_cast<uint32_t*>(&hb);
    ul.x = *reinterpret_cast<uint32_t*>(&la); ul.y = *reinterpret_cast<uint32_t*>(&lb);
    reinterpret_cast<uint2*>(oh)[i] = uh;
    reinterpret_cast<uint2*>(ol)[i] = ul;
}

__global__ void transpose_split(const float* __restrict__ in,
                                __half* __restrict__ oh, __half* __restrict__ ol, int R, int C)
{
    __shared__ float t[32][33];
    const int bc = blockIdx.x * 32, br = blockIdx.y * 32;
    const int x = threadIdx.x, y = threadIdx.y;
#pragma unroll
    for (int j = 0; j < 32; j += 8)
        t[y + j][x] = in[(size_t)(br + y + j) * C + bc + x];
    __syncthreads();
#pragma unroll
    for (int j = 0; j < 32; j += 8) {
        const float v = t[x][y + j];
        const __half h = __float2half_rn(v);
        const size_t o = (size_t)(bc + y + j) * R + br + x;
        oh[o] = h;
        ol[o] = __float2half_rn(v - __half2float(h));
    }
}

// ---------------------------------------------------------------------------
extern "C" void kernel_launch(void* const* d_in, const int* in_sizes, int n_in,
                              void* d_out, int out_size)
{
    const float* x  = (const float*)d_in[0];
    const float* Wq = (const float*)d_in[1];
    const float* Wk = (const float*)d_in[2];
    const float* Wv = (const float*)d_in[3];
    const float* Wo = (const float*)d_in[4];
    float* out = (float*)d_out;

    cudaFuncSetAttribute(gemm_mma<0, 2, 0>, cudaFuncAttributeMaxDynamicSharedMemorySize, SMEMSZ);
    cudaFuncSetAttribute(gemm_mma<1, 2, 0>, cudaFuncAttributeMaxDynamicSharedMemorySize, SMEMSZ);
    cudaFuncSetAttribute(gemm_mma<0, 2, 1>, cudaFuncAttributeMaxDynamicSharedMemorySize, SMEMSZ);
    cudaFuncSetAttribute(pv_fused, cudaFuncAttributeMaxDynamicSharedMemorySize, PV_SMEM);

    __half *xh, *xl, *wqth, *wqtl, *wkth, *wktl, *wvth, *wvtl, *woth, *wotl;
    __half *qh, *ql, *kh, *kl, *vth, *vtl, *yh, *yl;
    float *vf, *stats, *pm, *ps;
    cudaGetSymbolAddress((void**)&xh, g_xh);     cudaGetSymbolAddress((void**)&xl, g_xl);
    cudaGetSymbolAddress((void**)&wqth, g_wqth); cudaGetSymbolAddress((void**)&wqtl, g_wqtl);
    cudaGetSymbolAddress((void**)&wkth, g_wkth); cudaGetSymbolAddress((void**)&wktl, g_wktl);
    cudaGetSymbolAddress((void**)&wvth, g_wvth); cudaGetSymbolAddress((void**)&wvtl, g_wvtl);
    cudaGetSymbolAddress((void**)&woth, g_woth); cudaGetSymbolAddress((void**)&wotl, g_wotl);
    cudaGetSymbolAddress((void**)&qh, g_qh);     cudaGetSymbolAddress((void**)&ql, g_ql);
    cudaGetSymbolAddress((void**)&kh, g_kh);     cudaGetSymbolAddress((void**)&kl, g_kl);
    cudaGetSymbolAddress((void**)&vf, g_vf);
    cudaGetSymbolAddress((void**)&vth, g_vth);   cudaGetSymbolAddress((void**)&vtl, g_vtl);
    cudaGetSymbolAddress((void**)&yh, g_yh);     cudaGetSymbolAddress((void**)&yl, g_yl);
    cudaGetSymbolAddress((void**)&stats, g_stats);
    cudaGetSymbolAddress((void**)&pm, g_pm);     cudaGetSymbolAddress((void**)&ps, g_ps);

    const size_t ySz = (size_t)SEQ * FEAT;
    const size_t aSz = (size_t)NH * SEQ * SEQ;
    float* attn;
    if ((size_t)out_size >= ySz + aSz) attn = out + ySz;
    else cudaGetSymbolAddress((void**)&attn, g_attn_fb);

    // Prep: split x, transpose+split weights
    convert_split<<<(SEQ * FEAT / 4 + 255) / 256, 256>>>(x, xh, xl, SEQ * FEAT / 4);
    dim3 tb(32, 8);
    transpose_split<<<dim3(HID / 32, FEAT / 32), tb>>>(Wq, wqth, wqtl, FEAT, HID);
    transpose_split<<<dim3(HID / 32, FEAT / 32), tb>>>(Wk, wkth, wktl, FEAT, HID);
    transpose_split<<<dim3(HID / 32, FEAT / 32), tb>>>(Wv, wvth, wvtl, FEAT, HID);
    transpose_split<<<dim3(FEAT / 32, HID / 32), tb>>>(Wo, woth, wotl, HID, FEAT);

    // QKV projections: 2-term
    gemm_mma<1, 2, 0><<<dim3(HID / 128, SEQ / 128, 1), 256, SMEMSZ>>>(
        xh, xl, wqth, wqtl, nullptr, qh, ql, nullptr, nullptr,
        FEAT, FEAT, FEAT, HID, 1.0f, 0, 0, 0);
    gemm_mma<1, 2, 0><<<dim3(HID / 128, SEQ / 128, 1), 256, SMEMSZ>>>(
        xh, xl, wkth, wktl, nullptr, kh, kl, nullptr, nullptr,
        FEAT, FEAT, FEAT, HID, 1.0f, 0, 0, 0);
    gemm_mma<0, 2, 0><<<dim3(HID / 128, SEQ / 128, 1), 256, SMEMSZ>>>(
        xh, xl, wvth, wvtl, vf, nullptr, nullptr, nullptr, nullptr,
        FEAT, FEAT, FEAT, HID, 1.0f, 0, 0, 0);
    transpose_split<<<dim3(HID / 32, SEQ / 32), tb>>>(vf, vth, vtl, SEQ, HID);

    // Scores: 2-term (K fp16-rounded), fp32 scaled scores + fused softmax partials
    const float alpha = 0.08838834764831845f; // 1/sqrt(128)
    gemm_mma<0, 2, 1><<<dim3(SEQ / 128, SEQ / 128, NH), 256, SMEMSZ>>>(
        qh, ql, kh, kl, attn, nullptr, nullptr, pm, ps,
        DK, HID, HID, SEQ, alpha,
        (size_t)DK, (size_t)DK, (size_t)SEQ * SEQ);

    // Combine partials into final (max, 1/sum)
    combine_stats<<<NROWS / 8, 256>>>(pm, ps, stats);

    // Fused normalize + PV (1-term)
    pv_fused<<<dim3(1, SEQ / 128, NH), 256, PV_SMEM>>>(attn, stats, vth, yh, yl);

    // Output projection: 2-term
    gemm_mma<0, 2, 0><<<dim3(FEAT / 128, SEQ / 128, 1), 256, SMEMSZ>>>(
        yh, yl, woth, wotl, out, nullptr, nullptr, nullptr, nullptr,
        HID, HID, HID, FEAT, 1.0f, 0, 0, 0);
}

// round 9
// speedup vs baseline: 3.7877x; 1.2034x over previous
#include <cuda_runtime.h>
#include <cuda_fp16.h>
#include <cstdint>
#include <math.h>

#define SEQ 4096
#define FEAT 1024
#define HID 1024
#define NH 8
#define DK 128
#define NROWS (NH * SEQ)
#define NBX 32   // score col-blocks per row

// ---------------------------------------------------------------------------
// Device-global scratch (allocation-free per harness rules)
// ---------------------------------------------------------------------------
__device__ __half g_xh[(size_t)SEQ * FEAT], g_xl[(size_t)SEQ * FEAT];
__device__ __half g_wqth[(size_t)HID * FEAT];
__device__ __half g_wkth[(size_t)HID * FEAT];
__device__ __half g_wvth[(size_t)HID * FEAT];
__device__ __half g_woth[(size_t)FEAT * HID], g_wotl[(size_t)FEAT * HID];
__device__ __half g_qh[(size_t)SEQ * HID];
__device__ __half g_kh[(size_t)SEQ * HID];
__device__ float  g_vf[(size_t)SEQ * HID];
__device__ __half g_vth[(size_t)HID * SEQ], g_vtl[(size_t)HID * SEQ];
__device__ __half g_yh[(size_t)SEQ * HID], g_yl[(size_t)SEQ * HID];
__device__ float  g_stats[2 * NROWS];
__device__ float  g_pm[(size_t)NROWS * NBX], g_ps[(size_t)NROWS * NBX];
__device__ float  g_attn_fb[(size_t)NH * SEQ * SEQ];

// ---------------------------------------------------------------------------
// PTX helpers (arch-agnostic: cp.async sm_80+, ldmatrix sm_75+, mma sm_80+)
// ---------------------------------------------------------------------------
__device__ __forceinline__ uint32_t s2u(const void* p) {
    uint32_t a;
    asm("{ .reg .u64 t; cvta.to.shared.u64 t, %1; cvt.u32.u64 %0, t; }" : "=r"(a) : "l"(p));
    return a;
}
__device__ __forceinline__ void cpa16(uint32_t d, const void* s) {
    asm volatile("cp.async.cg.shared.global [%0], [%1], 16;" :: "r"(d), "l"(s));
}
__device__ __forceinline__ void cpcommit() { asm volatile("cp.async.commit_group;"); }
template <int N>
__device__ __forceinline__ void cpwait() { asm volatile("cp.async.wait_group %0;" :: "n"(N)); }

__device__ __forceinline__ void ldm4(uint32_t& r0, uint32_t& r1, uint32_t& r2, uint32_t& r3, uint32_t a) {
    asm volatile("ldmatrix.sync.aligned.m8n8.x4.shared.b16 {%0,%1,%2,%3}, [%4];"
                 : "=r"(r0), "=r"(r1), "=r"(r2), "=r"(r3) : "r"(a));
}
__device__ __forceinline__ void mma16816(float* c, const uint32_t* a, const uint32_t* b) {
    asm volatile(
        "mma.sync.aligned.m16n8k16.row.col.f32.f16.f16.f32 "
        "{%0,%1,%2,%3}, {%4,%5,%6,%7}, {%8,%9}, {%0,%1,%2,%3};"
        : "+f"(c[0]), "+f"(c[1]), "+f"(c[2]), "+f"(c[3])
        : "r"(a[0]), "r"(a[1]), "r"(a[2]), "r"(a[3]), "r"(b[0]), "r"(b[1]));
}

// ---------------------------------------------------------------------------
// Split-fp16 tensor-core GEMM: C[M,N] = alpha * A[M,K] @ B[N,K]^T
// TERMS=1: Ah·Bh.  TERMS=2: (Ah+Al)·Bh.  TERMS=3: (Ah+Al)·Bh + Ah·Bl.
// MODE 0: fp32 C.  MODE 1: fp16 hi/lo C pair.  MODE 2: fp16 single C.
// STATS 1: also emit per-CTA row softmax partials (max, sum-exp) to pm/ps.
// ---------------------------------------------------------------------------
#define LDT_B 80
#define TILE_B (128 * LDT_B)
#define STAGE_B (4 * TILE_B)
#define SMEMSZ (2 * STAGE_B)

template <int MODE, int TERMS, int STATS>
__global__ void __launch_bounds__(256) gemm_mma(
    const __half* __restrict__ Ah, const __half* __restrict__ Al,
    const __half* __restrict__ Bh, const __half* __restrict__ Bl,
    float* __restrict__ Cf, __half* __restrict__ Ch, __half* __restrict__ Cl,
    float* __restrict__ pm, float* __restrict__ ps,
    int K, int lda, int ldb, int ldc, float alpha,
    size_t sA, size_t sB, size_t sC)
{
    extern __shared__ char sm[];
    const uint32_t smb = s2u(sm);
    __shared__ float srm[STATS ? 128 : 1][4];
    __shared__ float srs[STATS ? 128 : 1][4];

    const int tid = threadIdx.x;
    const int wid = tid >> 5;
    const int lane = tid & 31;
    const int warp_m = wid & 1;
    const int warp_n = wid >> 1;

    Ah += blockIdx.z * sA;
    if constexpr (TERMS >= 2) Al += blockIdx.z * sA;
    Bh += blockIdx.z * sB;
    if constexpr (TERMS == 3) Bl += blockIdx.z * sB;
    const size_t cOff = blockIdx.z * sC;

    const int bm = blockIdx.y * 128;
    const int bn = blockIdx.x * 128;

    const int c_row = tid >> 2;
    const int c_seg = tid & 3;

    const uint32_t aoff = (uint32_t)(((lane & 7) + ((lane >> 3) & 1) * 8) * LDT_B + (lane >> 4) * 16);
    const uint32_t boff = (uint32_t)(((lane >> 4) * 8 + (lane & 7)) * LDT_B + ((lane >> 3) & 1) * 16);

    float acc[4][4][4];
#pragma unroll
    for (int i = 0; i < 4; i++)
#pragma unroll
        for (int j = 0; j < 4; j++)
#pragma unroll
            for (int q = 0; q < 4; q++) acc[i][j][q] = 0.0f;

    const int nch = K >> 5;

    auto load_chunk = [&](int stage, int kb) {
        const uint32_t sb = smb + stage * STAGE_B;
#pragma unroll
        for (int s = 0; s < 2; s++) {
            const int row = c_row + s * 64;
            const uint32_t so = (uint32_t)(row * LDT_B + c_seg * 16);
            const size_t go = (size_t)row * lda + kb + c_seg * 8;
            cpa16(sb + so,              Ah + (size_t)bm * lda + go);
            if constexpr (TERMS >= 2)
                cpa16(sb + TILE_B + so, Al + (size_t)bm * lda + go);
            const size_t gob = (size_t)row * ldb + kb + c_seg * 8;
            cpa16(sb + 2 * TILE_B + so, Bh + (size_t)bn * ldb + gob);
            if constexpr (TERMS == 3)
                cpa16(sb + 3 * TILE_B + so, Bl + (size_t)bn * ldb + gob);
        }
        cpcommit();
    };

    load_chunk(0, 0);

    for (int c = 0; c < nch; c++) {
        if (c + 1 < nch) { load_chunk((c + 1) & 1, (c + 1) << 5); cpwait<1>(); }
        else             { cpwait<0>(); }
        __syncthreads();

        const uint32_t sb = smb + (c & 1) * STAGE_B;
        const uint32_t aH = sb + (uint32_t)(warp_m * 64) * LDT_B;
        const uint32_t aL = aH + TILE_B;
        const uint32_t bH = sb + 2 * TILE_B + (uint32_t)(warp_n * 32) * LDT_B;
        const uint32_t bL = bH + TILE_B;

#pragma unroll
        for (int ks = 0; ks < 2; ks++) {
            const uint32_t kb2 = ks * 32;
            uint32_t A[4][4], B[4][2];
#pragma unroll
            for (int mt = 0; mt < 4; mt++)
                ldm4(A[mt][0], A[mt][1], A[mt][2], A[mt][3],
                     aH + (uint32_t)(mt * 16) * LDT_B + aoff + kb2);
#pragma unroll
            for (int p = 0; p < 2; p++) {
                uint32_t r0, r1, r2, r3;
                ldm4(r0, r1, r2, r3, bH + (uint32_t)(p * 16) * LDT_B + boff + kb2);
                B[p * 2][0] = r0; B[p * 2][1] = r1;
                B[p * 2 + 1][0] = r2; B[p * 2 + 1][1] = r3;
            }
#pragma unroll
            for (int mt = 0; mt < 4; mt++)
#pragma unroll
                for (int nt = 0; nt < 4; nt++)
                    mma16816(acc[mt][nt], A[mt], B[nt]);

            if constexpr (TERMS == 3) {
                uint32_t BL[4][2];
#pragma unroll
                for (int p = 0; p < 2; p++) {
                    uint32_t r0, r1, r2, r3;
                    ldm4(r0, r1, r2, r3, bL + (uint32_t)(p * 16) * LDT_B + boff + kb2);
                    BL[p * 2][0] = r0; BL[p * 2][1] = r1;
                    BL[p * 2 + 1][0] = r2; BL[p * 2 + 1][1] = r3;
                }
#pragma unroll
                for (int mt = 0; mt < 4; mt++)
#pragma unroll
                    for (int nt = 0; nt < 4; nt++)
                        mma16816(acc[mt][nt], A[mt], BL[nt]);
            }
            if constexpr (TERMS >= 2) {
#pragma unroll
                for (int mt = 0; mt < 4; mt++)
                    ldm4(A[mt][0], A[mt][1], A[mt][2], A[mt][3],
                         aL + (uint32_t)(mt * 16) * LDT_B + aoff + kb2);
#pragma unroll
                for (int mt = 0; mt < 4; mt++)
#pragma unroll
                    for (int nt = 0; nt < 4; nt++)
                        mma16816(acc[mt][nt], A[mt], B[nt]);
            }
        }
        __syncthreads();
    }

    const int g = lane >> 2;
    const int tq = lane & 3;
#pragma unroll
    for (int mt = 0; mt < 4; mt++) {
        const int row0 = bm + warp_m * 64 + mt * 16 + g;
        float v0s[4], v1s[4], v2s[4], v3s[4];
#pragma unroll
        for (int nt = 0; nt < 4; nt++) {
            const int col = bn + warp_n * 32 + nt * 8 + tq * 2;
            const float v0 = acc[mt][nt][0] * alpha;
            const float v1 = acc[mt][nt][1] * alpha;
            const float v2 = acc[mt][nt][2] * alpha;
            const float v3 = acc[mt][nt][3] * alpha;
            v0s[nt] = v0; v1s[nt] = v1; v2s[nt] = v2; v3s[nt] = v3;
            if constexpr (MODE == 0) {
                *reinterpret_cast<float2*>(Cf + cOff + (size_t)row0 * ldc + col) = make_float2(v0, v1);
                *reinterpret_cast<float2*>(Cf + cOff + (size_t)(row0 + 8) * ldc + col) = make_float2(v2, v3);
            } else if constexpr (MODE == 1) {
                const __half h0 = __float2half_rn(v0), h1 = __float2half_rn(v1);
                const __half h2 = __float2half_rn(v2), h3 = __float2half_rn(v3);
                const __half l0 = __float2half_rn(v0 - __half2float(h0));
                const __half l1 = __float2half_rn(v1 - __half2float(h1));
                const __half l2 = __float2half_rn(v2 - __half2float(h2));
                const __half l3 = __float2half_rn(v3 - __half2float(h3));
                *reinterpret_cast<__half2*>(Ch + cOff + (size_t)row0 * ldc + col) = __halves2half2(h0, h1);
                *reinterpret_cast<__half2*>(Ch + cOff + (size_t)(row0 + 8) * ldc + col) = __halves2half2(h2, h3);
                *reinterpret_cast<__half2*>(Cl + cOff + (size_t)row0 * ldc + col) = __halves2half2(l0, l1);
                *reinterpret_cast<__half2*>(Cl + cOff + (size_t)(row0 + 8) * ldc + col) = __halves2half2(l2, l3);
            } else {
                *reinterpret_cast<__half2*>(Ch + cOff + (size_t)row0 * ldc + col) =
                    __floats2half2_rn(v0, v1);
                *reinterpret_cast<__half2*>(Ch + cOff + (size_t)(row0 + 8) * ldc + col) =
                    __floats2half2_rn(v2, v3);
            }
        }
        if constexpr (STATS) {
            float m0 = -1e30f, m1 = -1e30f;
#pragma unroll
            for (int nt = 0; nt < 4; nt++) {
                m0 = fmaxf(m0, fmaxf(v0s[nt], v1s[nt]));
                m1 = fmaxf(m1, fmaxf(v2s[nt], v3s[nt]));
            }
            float s0 = 0.0f, s1 = 0.0f;
#pragma unroll
            for (int nt = 0; nt < 4; nt++) {
                s0 += __expf(v0s[nt] - m0) + __expf(v1s[nt] - m0);
                s1 += __expf(v2s[nt] - m1) + __expf(v3s[nt] - m1);
            }
#pragma unroll
            for (int o = 1; o <= 2; o <<= 1) {
                float om = __shfl_xor_sync(0xffffffffu, m0, o);
                float os = __shfl_xor_sync(0xffffffffu, s0, o);
                float nm = fmaxf(m0, om);
                s0 = s0 * __expf(m0 - nm) + os * __expf(om - nm);
                m0 = nm;
                om = __shfl_xor_sync(0xffffffffu, m1, o);
                os = __shfl_xor_sync(0xffffffffu, s1, o);
                nm = fmaxf(m1, om);
                s1 = s1 * __expf(m1 - nm) + os * __expf(om - nm);
                m1 = nm;
            }
            if (tq == 0) {
                const int rl = warp_m * 64 + mt * 16 + g;
                srm[rl][warp_n] = m0; srs[rl][warp_n] = s0;
                srm[rl + 8][warp_n] = m1; srs[rl + 8][warp_n] = s1;
            }
        }
    }
    if constexpr (STATS) {
        __syncthreads();
        if (tid < 128) {
            float m = srm[tid][0], s = srs[tid][0];
#pragma unroll
            for (int w = 1; w < 4; w++) {
                const float om = srm[tid][w], os = srs[tid][w];
                const float nm = fmaxf(m, om);
                s = s * __expf(m - nm) + os * __expf(om - nm);
                m = nm;
            }
            const size_t idx = ((size_t)blockIdx.z * SEQ + bm + tid) * NBX + blockIdx.x;
            pm[idx] = m; ps[idx] = s;
        }
    }
}

// ---------------------------------------------------------------------------
// Combine per-CTA partials (NBX=32 per row) into final (max, 1/sum)
// ---------------------------------------------------------------------------
__global__ void __launch_bounds__(256) combine_stats(const float* __restrict__ pm,
                                                     const float* __restrict__ ps,
                                                     float* __restrict__ stats)
{
    const int row = blockIdx.x * 8 + (threadIdx.x >> 5);
    const int lane = threadIdx.x & 31;
    float m = pm[(size_t)row * NBX + lane];
    float s = ps[(size_t)row * NBX + lane];
#pragma unroll
    for (int o = 16; o; o >>= 1) {
        const float om = __shfl_xor_sync(0xffffffffu, m, o);
        const float os = __shfl_xor_sync(0xffffffffu, s, o);
        const float nm = fmaxf(m, om);
        s = s * __expf(m - nm) + os * __expf(om - nm);
        m = nm;
    }
    if (lane == 0) {
        stats[row] = m;
        stats[NROWS + row] = 1.0f / s;
    }
}

// ---------------------------------------------------------------------------
// Fused softmax-normalize + PV GEMM, 1-term (V single fp16).
// ---------------------------------------------------------------------------
#define PV_TILE (128 * LDT_B)
#define PV_SMEM (4 * PV_TILE)

__global__ void __launch_bounds__(256) pv_fused(
    float* __restrict__ attn, const float* __restrict__ stats,
    const __half* __restrict__ vth,
    __half* __restrict__ yh, __half* __restrict__ yl)
{
    extern __shared__ char sm[];
    const uint32_t smb = s2u(sm);
    __shared__ float sm_m[128], sm_inv[128];

    const int tid = threadIdx.x;
    const int wid = tid >> 5, lane = tid & 31;
    const int warp_m = wid & 1, warp_n = wid >> 1;
    const int z = blockIdx.z;
    const int bm = blockIdx.y * 128;

    float* ab = attn + (size_t)z * SEQ * SEQ + (size_t)bm * SEQ;
    const __half* vhb = vth + (size_t)(z * DK) * SEQ;

    const int grow = z * SEQ + bm;
    if (tid < 128) {
        sm_m[tid] = stats[grow + tid];
        sm_inv[tid] = stats[NROWS + grow + tid];
    }
    __syncthreads();

    float4 pre[4];
    auto ldA = [&](int kb) {
#pragma unroll
        for (int i = 0; i < 4; i++) {
            const int idx = tid + i * 256;
            pre[i] = *reinterpret_cast<const float4*>(
                ab + (size_t)(idx >> 3) * SEQ + kb + (idx & 7) * 4);
        }
    };
    auto expsts = [&](int kb, int st) {
        const uint32_t as = smb + st * PV_TILE;
#pragma unroll
        for (int i = 0; i < 4; i++) {
            const int idx = tid + i * 256;
            const int r = idx >> 3, sg = idx & 7;
            const float m = sm_m[r], inv = sm_inv[r];
            float4 p;
            p.x = __expf(pre[i].x - m) * inv;
            p.y = __expf(pre[i].y - m) * inv;
            p.z = __expf(pre[i].z - m) * inv;
            p.w = __expf(pre[i].w - m) * inv;
            *reinterpret_cast<float4*>(ab + (size_t)r * SEQ + kb + sg * 4) = p;
            __half2 h01 = __floats2half2_rn(p.x, p.y);
            __half2 h23 = __floats2half2_rn(p.z, p.w);
            asm volatile("st.shared.v2.b32 [%0], {%1, %2};"
                         :: "r"(as + (uint32_t)(r * LDT_B + sg * 8)),
                            "r"(*reinterpret_cast<uint32_t*>(&h01)),
                            "r"(*reinterpret_cast<uint32_t*>(&h23)));
        }
    };
    auto ldV = [&](int kb, int st) {
        const uint32_t vs = smb + 2 * PV_TILE + st * PV_TILE;
#pragma unroll
        for (int i = 0; i < 2; i++) {
            const int idx = tid + i * 256;
            const int r = idx >> 2, sg = idx & 3;
            cpa16(vs + (uint32_t)(r * LDT_B + sg * 16),
                  vhb + (size_t)r * SEQ + kb + sg * 8);
        }
        cpcommit();
    };

    const uint32_t aoff = (uint32_t)(((lane & 7) + ((lane >> 3) & 1) * 8) * LDT_B + (lane >> 4) * 16);
    const uint32_t boff = (uint32_t)(((lane >> 4) * 8 + (lane & 7)) * LDT_B + ((lane >> 3) & 1) * 16);

    float acc[4][4][4];
#pragma unroll
    for (int i = 0; i < 4; i++)
#pragma unroll
        for (int j = 0; j < 4; j++)
#pragma unroll
            for (int q = 0; q < 4; q++) acc[i][j][q] = 0.0f;

    ldA(0); ldV(0, 0);
    expsts(0, 0);

    const int nch = SEQ / 32;
    for (int c = 0; c < nch; c++) {
        if (c + 1 < nch) { ldA((c + 1) * 32); ldV((c + 1) * 32, (c + 1) & 1); cpwait<1>(); }
        else             { cpwait<0>(); }
        __syncthreads();

        const uint32_t as  = smb + (c & 1) * PV_TILE;
        const uint32_t vhs = smb + 2 * PV_TILE + (c & 1) * PV_TILE;

#pragma unroll
        for (int ks = 0; ks < 2; ks++) {
            const uint32_t kb2 = ks * 32;
            uint32_t A[4][4], B[4][2];
#pragma unroll
            for (int mt = 0; mt < 4; mt++)
                ldm4(A[mt][0], A[mt][1], A[mt][2], A[mt][3],
                     as + (uint32_t)((warp_m * 64 + mt * 16) * LDT_B) + aoff + kb2);
#pragma unroll
            for (int p = 0; p < 2; p++) {
                uint32_t r0, r1, r2, r3;
                ldm4(r0, r1, r2, r3, vhs + (uint32_t)((warp_n * 32 + p * 16) * LDT_B) + boff + kb2);
                B[p * 2][0] = r0; B[p * 2][1] = r1;
                B[p * 2 + 1][0] = r2; B[p * 2 + 1][1] = r3;
            }
#pragma unroll
            for (int mt = 0; mt < 4; mt++)
#pragma unroll
                for (int nt = 0; nt < 4; nt++)
                    mma16816(acc[mt][nt], A[mt], B[nt]);
        }
        if (c + 1 < nch) expsts((c + 1) * 32, (c + 1) & 1);
        __syncthreads();
    }

    const int g = lane >> 2, tq = lane & 3;
#pragma unroll
    for (int mt = 0; mt < 4; mt++) {
        const int row0 = bm + warp_m * 64 + mt * 16 + g;
#pragma unroll
        for (int nt = 0; nt < 4; nt++) {
            const int col = z * DK + warp_n * 32 + nt * 8 + tq * 2;
            const float v0 = acc[mt][nt][0], v1 = acc[mt][nt][1];
            const float v2 = acc[mt][nt][2], v3 = acc[mt][nt][3];
            const __half h0 = __float2half_rn(v0), h1 = __float2half_rn(v1);
            const __half h2 = __float2half_rn(v2), h3 = __float2half_rn(v3);
            const __half l0 = __float2half_rn(v0 - __half2float(h0));
            const __half l1 = __float2half_rn(v1 - __half2float(h1));
            const __half l2 = __float2half_rn(v2 - __half2float(h2));
            const __half l3 = __float2half_rn(v3 - __half2float(h3));
            *reinterpret_cast<__half2*>(yh + (size_t)row0 * HID + col) = __halves2half2(h0, h1);
            *reinterpret_cast<__half2*>(yh + (size_t)(row0 + 8) * HID + col) = __halves2half2(h2, h3);
            *reinterpret_cast<__half2*>(yl + (size_t)row0 * HID + col) = __halves2half2(l0, l1);
            *reinterpret_cast<__half2*>(yl + (size_t)(row0 + 8) * HID + col) = __halves2half2(l2, l3);
        }
    }
}

// ---------------------------------------------------------------------------
// Prep kernels
// ---------------------------------------------------------------------------
__global__ void convert_split(const float* __restrict__ in,
                              __half* __restrict__ oh, __half* __restrict__ ol, int n4)
{
    const int i = blockIdx.x * blockDim.x + threadIdx.x;
    if (i >= n4) return;
    const float4 v = reinterpret_cast<const float4*>(in)[i];
    const __half h0 = __float2half_rn(v.x), h1 = __float2half_rn(v.y);
    const __half h2 = __float2half_rn(v.z), h3 = __float2half_rn(v.w);
    const __half l0 = __float2half_rn(v.x - __half2float(h0));
    const __half l1 = __float2half_rn(v.y - __half2float(h1));
    const __half l2 = __float2half_rn(v.z - __half2float(h2));
    const __half l3 = __float2half_rn(v.w - __half2float(h3));
    __half2 ha = __halves2half2(h0, h1), hb = __halves2half2(h2, h3);
    __half2 la = __halves2half2(l0, l1), lb = __halves2half2(l2, l3);
    uint2 uh, ul;
    uh.x = *reinterpret_cast<uint32_t*>(&ha); uh.y = *reinterpret_cast<uint32_t*>(&hb);
    ul.x = *reinterpret_cast<uint32_t*>(&la); ul.y = *reinterpret_cast<uint32_t*>(&lb);
    reinterpret_cast<uint2*>(oh)[i] = uh;
    reinterpret_cast<uint2*>(ol)[i] = ul;
}

// transpose fp32 [R][C] -> fp16 hi(/lo) [C][R]; SPLIT controls lo emission
template <int SPLIT>
__global__ void transpose_h(const float* __restrict__ in,
                            __half* __restrict__ oh, __half* __restrict__ ol, int R, int C)
{
    __shared__ float t[32][33];
    const int bc = blockIdx.x * 32, br = blockIdx.y * 32;
    const int x = threadIdx.x, y = threadIdx.y;
#pragma unroll
    for (int j = 0; j < 32; j += 8)
        t[y + j][x] = in[(size_t)(br + y + j) * C + bc + x];
    __syncthreads();
#pragma unroll
    for (int j = 0; j < 32; j += 8) {
        const float v = t[x][y + j];
        const __half h = __float2half_rn(v);
        const size_t o = (size_t)(bc + y + j) * R + br + x;
        oh[o] = h;
        if constexpr (SPLIT) ol[o] = __float2half_rn(v - __half2float(h));
    }
}

// ---------------------------------------------------------------------------
extern "C" void kernel_launch(void* const* d_in, const int* in_sizes, int n_in,
                              void* d_out, int out_size)
{
    const float* x  = (const float*)d_in[0];
    const float* Wq = (const float*)d_in[1];
    const float* Wk = (const float*)d_in[2];
    const float* Wv = (const float*)d_in[3];
    const float* Wo = (const float*)d_in[4];
    float* out = (float*)d_out;

    cudaFuncSetAttribute(gemm_mma<2, 1, 0>, cudaFuncAttributeMaxDynamicSharedMemorySize, SMEMSZ);
    cudaFuncSetAttribute(gemm_mma<0, 1, 0>, cudaFuncAttributeMaxDynamicSharedMemorySize, SMEMSZ);
    cudaFuncSetAttribute(gemm_mma<0, 1, 1>, cudaFuncAttributeMaxDynamicSharedMemorySize, SMEMSZ);
    cudaFuncSetAttribute(gemm_mma<0, 2, 0>, cudaFuncAttributeMaxDynamicSharedMemorySize, SMEMSZ);
    cudaFuncSetAttribute(pv_fused, cudaFuncAttributeMaxDynamicSharedMemorySize, PV_SMEM);

    __half *xh, *xl, *wqth, *wkth, *wvth, *woth, *wotl;
    __half *qh, *kh, *vth, *vtl, *yh, *yl;
    float *vf, *stats, *pm, *ps;
    cudaGetSymbolAddress((void**)&xh, g_xh);     cudaGetSymbolAddress((void**)&xl, g_xl);
    cudaGetSymbolAddress((void**)&wqth, g_wqth);
    cudaGetSymbolAddress((void**)&wkth, g_wkth);
    cudaGetSymbolAddress((void**)&wvth, g_wvth);
    cudaGetSymbolAddress((void**)&woth, g_woth); cudaGetSymbolAddress((void**)&wotl, g_wotl);
    cudaGetSymbolAddress((void**)&qh, g_qh);
    cudaGetSymbolAddress((void**)&kh, g_kh);
    cudaGetSymbolAddress((void**)&vf, g_vf);
    cudaGetSymbolAddress((void**)&vth, g_vth);   cudaGetSymbolAddress((void**)&vtl, g_vtl);
    cudaGetSymbolAddress((void**)&yh, g_yh);     cudaGetSymbolAddress((void**)&yl, g_yl);
    cudaGetSymbolAddress((void**)&stats, g_stats);
    cudaGetSymbolAddress((void**)&pm, g_pm);     cudaGetSymbolAddress((void**)&ps, g_ps);

    const size_t ySz = (size_t)SEQ * FEAT;
    const size_t aSz = (size_t)NH * SEQ * SEQ;
    float* attn;
    if ((size_t)out_size >= ySz + aSz) attn = out + ySz;
    else cudaGetSymbolAddress((void**)&attn, g_attn_fb);

    // Prep: split x (hi/lo; lo used only by out-proj path via Y), transpose weights
    convert_split<<<(SEQ * FEAT / 4 + 255) / 256, 256>>>(x, xh, xl, SEQ * FEAT / 4);
    dim3 tb(32, 8);
    transpose_h<0><<<dim3(HID / 32, FEAT / 32), tb>>>(Wq, wqth, nullptr, FEAT, HID);
    transpose_h<0><<<dim3(HID / 32, FEAT / 32), tb>>>(Wk, wkth, nullptr, FEAT, HID);
    transpose_h<0><<<dim3(HID / 32, FEAT / 32), tb>>>(Wv, wvth, nullptr, FEAT, HID);
    transpose_h<1><<<dim3(FEAT / 32, HID / 32), tb>>>(Wo, woth, wotl, HID, FEAT);

    // Q, K projections: 1-term, single fp16 out
    gemm_mma<2, 1, 0><<<dim3(HID / 128, SEQ / 128, 1), 256, SMEMSZ>>>(
        xh, nullptr, wqth, nullptr, nullptr, qh, nullptr, nullptr, nullptr,
        FEAT, FEAT, FEAT, HID, 1.0f, 0, 0, 0);
    gemm_mma<2, 1, 0><<<dim3(HID / 128, SEQ / 128, 1), 256, SMEMSZ>>>(
        xh, nullptr, wkth, nullptr, nullptr, kh, nullptr, nullptr, nullptr,
        FEAT, FEAT, FEAT, HID, 1.0f, 0, 0, 0);
    // V projection: 1-term, fp32 out -> transpose to fp16 [HID][SEQ]
    gemm_mma<0, 1, 0><<<dim3(HID / 128, SEQ / 128, 1), 256, SMEMSZ>>>(
        xh, nullptr, wvth, nullptr, vf, nullptr, nullptr, nullptr, nullptr,
        FEAT, FEAT, FEAT, HID, 1.0f, 0, 0, 0);
    transpose_h<0><<<dim3(HID / 32, SEQ / 32), tb>>>(vf, vth, nullptr, SEQ, HID);

    // Scores: 1-term fp16, fp32 scaled scores + fused softmax partials
    const float alpha = 0.08838834764831845f; // 1/sqrt(128)
    gemm_mma<0, 1, 1><<<dim3(SEQ / 128, SEQ / 128, NH), 256, SMEMSZ>>>(
        qh, nullptr, kh, nullptr, attn, nullptr, nullptr, pm, ps,
        DK, HID, HID, SEQ, alpha,
        (size_t)DK, (size_t)DK, (size_t)SEQ * SEQ);

    // Combine partials into final (max, 1/sum)
    combine_stats<<<NROWS / 8, 256>>>(pm, ps, stats);

    // Fused normalize + PV (1-term)
    pv_fused<<<dim3(1, SEQ / 128, NH), 256, PV_SMEM>>>(attn, stats, vth, yh, yl);

    // Output projection: 2-term (Y hi/lo x Wo fp16)
    gemm_mma<0, 2, 0><<<dim3(FEAT / 128, SEQ / 128, 1), 256, SMEMSZ>>>(
        yh, yl, woth, wotl, out, nullptr, nullptr, nullptr, nullptr,
        HID, HID, HID, FEAT, 1.0f, 0, 0, 0);
}

// round 10
// speedup vs baseline: 4.1882x; 1.1057x over previous
#include <cuda_runtime.h>
#include <cuda_fp16.h>
#include <cstdint>
#include <math.h>

#define SEQ 4096
#define FEAT 1024
#define HID 1024
#define NH 8
#define DK 128
#define NROWS (NH * SEQ)
#define NBX 32   // score col-blocks per row

// ---------------------------------------------------------------------------
// Device-global scratch (allocation-free per harness rules)
// ---------------------------------------------------------------------------
__device__ __half g_xh[(size_t)SEQ * FEAT];
__device__ __half g_wt[(size_t)3 * HID * FEAT];          // Wq^T, Wk^T, Wv^T (fp16)
__device__ __half g_woth[(size_t)FEAT * HID], g_wotl[(size_t)FEAT * HID];
__device__ __half g_qkv[(size_t)3 * SEQ * HID];          // Q, K, V (fp16)
__device__ __half g_vth[(size_t)HID * SEQ];              // V^T
__device__ __half g_sh[(size_t)NH * SEQ * SEQ];          // raw fp16 scaled scores
__device__ __half g_yh[(size_t)SEQ * HID], g_yl[(size_t)SEQ * HID];
__device__ float  g_stats[2 * NROWS];
__device__ float  g_pm[(size_t)NROWS * NBX], g_ps[(size_t)NROWS * NBX];
__device__ float  g_attn_fb[(size_t)NH * SEQ * SEQ];

// ---------------------------------------------------------------------------
// PTX helpers (arch-agnostic: cp.async sm_80+, ldmatrix sm_75+, mma sm_80+)
// ---------------------------------------------------------------------------
__device__ __forceinline__ uint32_t s2u(const void* p) {
    uint32_t a;
    asm("{ .reg .u64 t; cvta.to.shared.u64 t, %1; cvt.u32.u64 %0, t; }" : "=r"(a) : "l"(p));
    return a;
}
__device__ __forceinline__ void cpa16(uint32_t d, const void* s) {
    asm volatile("cp.async.cg.shared.global [%0], [%1], 16;" :: "r"(d), "l"(s));
}
__device__ __forceinline__ void cpcommit() { asm volatile("cp.async.commit_group;"); }
template <int N>
__device__ __forceinline__ void cpwait() { asm volatile("cp.async.wait_group %0;" :: "n"(N)); }

__device__ __forceinline__ void ldm4(uint32_t& r0, uint32_t& r1, uint32_t& r2, uint32_t& r3, uint32_t a) {
    asm volatile("ldmatrix.sync.aligned.m8n8.x4.shared.b16 {%0,%1,%2,%3}, [%4];"
                 : "=r"(r0), "=r"(r1), "=r"(r2), "=r"(r3) : "r"(a));
}
__device__ __forceinline__ void mma16816(float* c, const uint32_t* a, const uint32_t* b) {
    asm volatile(
        "mma.sync.aligned.m16n8k16.row.col.f32.f16.f16.f32 "
        "{%0,%1,%2,%3}, {%4,%5,%6,%7}, {%8,%9}, {%0,%1,%2,%3};"
        : "+f"(c[0]), "+f"(c[1]), "+f"(c[2]), "+f"(c[3])
        : "r"(a[0]), "r"(a[1]), "r"(a[2]), "r"(a[3]), "r"(b[0]), "r"(b[1]));
}

// ---------------------------------------------------------------------------
// Split-fp16 tensor-core GEMM: C[M,N] = alpha * A[M,K] @ B[N,K]^T
// TERMS=1: Ah·Bh.  TERMS=2: (Ah+Al)·Bh.
// MODE 0: fp32 C.  MODE 1: fp16 hi/lo C pair.  MODE 2: fp16 single C.
// STATS 1: per-CTA row softmax partials (max, sum-exp over ROUNDED values).
// ---------------------------------------------------------------------------
#define LDT_B 80
#define TILE_B (128 * LDT_B)
#define STAGE_B (4 * TILE_B)
#define SMEMSZ (2 * STAGE_B)

template <int MODE, int TERMS, int STATS>
__global__ void __launch_bounds__(256) gemm_mma(
    const __half* __restrict__ Ah, const __half* __restrict__ Al,
    const __half* __restrict__ Bh, const __half* __restrict__ Bl,
    float* __restrict__ Cf, __half* __restrict__ Ch, __half* __restrict__ Cl,
    float* __restrict__ pm, float* __restrict__ ps,
    int K, int lda, int ldb, int ldc, float alpha,
    size_t sA, size_t sB, size_t sC)
{
    extern __shared__ char sm[];
    const uint32_t smb = s2u(sm);
    __shared__ float srm[STATS ? 128 : 1][4];
    __shared__ float srs[STATS ? 128 : 1][4];

    const int tid = threadIdx.x;
    const int wid = tid >> 5;
    const int lane = tid & 31;
    const int warp_m = wid & 1;
    const int warp_n = wid >> 1;

    Ah += blockIdx.z * sA;
    if constexpr (TERMS >= 2) Al += blockIdx.z * sA;
    Bh += blockIdx.z * sB;
    if constexpr (TERMS == 3) Bl += blockIdx.z * sB;
    const size_t cOff = blockIdx.z * sC;

    const int bm = blockIdx.y * 128;
    const int bn = blockIdx.x * 128;

    const int c_row = tid >> 2;
    const int c_seg = tid & 3;

    const uint32_t aoff = (uint32_t)(((lane & 7) + ((lane >> 3) & 1) * 8) * LDT_B + (lane >> 4) * 16);
    const uint32_t boff = (uint32_t)(((lane >> 4) * 8 + (lane & 7)) * LDT_B + ((lane >> 3) & 1) * 16);

    float acc[4][4][4];
#pragma unroll
    for (int i = 0; i < 4; i++)
#pragma unroll
        for (int j = 0; j < 4; j++)
#pragma unroll
            for (int q = 0; q < 4; q++) acc[i][j][q] = 0.0f;

    const int nch = K >> 5;

    auto load_chunk = [&](int stage, int kb) {
        const uint32_t sb = smb + stage * STAGE_B;
#pragma unroll
        for (int s = 0; s < 2; s++) {
            const int row = c_row + s * 64;
            const uint32_t so = (uint32_t)(row * LDT_B + c_seg * 16);
            const size_t go = (size_t)row * lda + kb + c_seg * 8;
            cpa16(sb + so,              Ah + (size_t)bm * lda + go);
            if constexpr (TERMS >= 2)
                cpa16(sb + TILE_B + so, Al + (size_t)bm * lda + go);
            const size_t gob = (size_t)row * ldb + kb + c_seg * 8;
            cpa16(sb + 2 * TILE_B + so, Bh + (size_t)bn * ldb + gob);
            if constexpr (TERMS == 3)
                cpa16(sb + 3 * TILE_B + so, Bl + (size_t)bn * ldb + gob);
        }
        cpcommit();
    };

    load_chunk(0, 0);

    for (int c = 0; c < nch; c++) {
        if (c + 1 < nch) { load_chunk((c + 1) & 1, (c + 1) << 5); cpwait<1>(); }
        else             { cpwait<0>(); }
        __syncthreads();

        const uint32_t sb = smb + (c & 1) * STAGE_B;
        const uint32_t aH = sb + (uint32_t)(warp_m * 64) * LDT_B;
        const uint32_t aL = aH + TILE_B;
        const uint32_t bH = sb + 2 * TILE_B + (uint32_t)(warp_n * 32) * LDT_B;

#pragma unroll
        for (int ks = 0; ks < 2; ks++) {
            const uint32_t kb2 = ks * 32;
            uint32_t A[4][4], B[4][2];
#pragma unroll
            for (int mt = 0; mt < 4; mt++)
                ldm4(A[mt][0], A[mt][1], A[mt][2], A[mt][3],
                     aH + (uint32_t)(mt * 16) * LDT_B + aoff + kb2);
#pragma unroll
            for (int p = 0; p < 2; p++) {
                uint32_t r0, r1, r2, r3;
                ldm4(r0, r1, r2, r3, bH + (uint32_t)(p * 16) * LDT_B + boff + kb2);
                B[p * 2][0] = r0; B[p * 2][1] = r1;
                B[p * 2 + 1][0] = r2; B[p * 2 + 1][1] = r3;
            }
#pragma unroll
            for (int mt = 0; mt < 4; mt++)
#pragma unroll
                for (int nt = 0; nt < 4; nt++)
                    mma16816(acc[mt][nt], A[mt], B[nt]);

            if constexpr (TERMS >= 2) {
#pragma unroll
                for (int mt = 0; mt < 4; mt++)
                    ldm4(A[mt][0], A[mt][1], A[mt][2], A[mt][3],
                         aL + (uint32_t)(mt * 16) * LDT_B + aoff + kb2);
#pragma unroll
                for (int mt = 0; mt < 4; mt++)
#pragma unroll
                    for (int nt = 0; nt < 4; nt++)
                        mma16816(acc[mt][nt], A[mt], B[nt]);
            }
        }
        __syncthreads();
    }

    const int g = lane >> 2;
    const int tq = lane & 3;
#pragma unroll
    for (int mt = 0; mt < 4; mt++) {
        const int row0 = bm + warp_m * 64 + mt * 16 + g;
        float v0s[4], v1s[4], v2s[4], v3s[4];
#pragma unroll
        for (int nt = 0; nt < 4; nt++) {
            const int col = bn + warp_n * 32 + nt * 8 + tq * 2;
            const float v0 = acc[mt][nt][0] * alpha;
            const float v1 = acc[mt][nt][1] * alpha;
            const float v2 = acc[mt][nt][2] * alpha;
            const float v3 = acc[mt][nt][3] * alpha;
            if constexpr (MODE == 0) {
                *reinterpret_cast<float2*>(Cf + cOff + (size_t)row0 * ldc + col) = make_float2(v0, v1);
                *reinterpret_cast<float2*>(Cf + cOff + (size_t)(row0 + 8) * ldc + col) = make_float2(v2, v3);
                v0s[nt] = v0; v1s[nt] = v1; v2s[nt] = v2; v3s[nt] = v3;
            } else if constexpr (MODE == 1) {
                const __half h0 = __float2half_rn(v0), h1 = __float2half_rn(v1);
                const __half h2 = __float2half_rn(v2), h3 = __float2half_rn(v3);
                const __half l0 = __float2half_rn(v0 - __half2float(h0));
                const __half l1 = __float2half_rn(v1 - __half2float(h1));
                const __half l2 = __float2half_rn(v2 - __half2float(h2));
                const __half l3 = __float2half_rn(v3 - __half2float(h3));
                *reinterpret_cast<__half2*>(Ch + cOff + (size_t)row0 * ldc + col) = __halves2half2(h0, h1);
                *reinterpret_cast<__half2*>(Ch + cOff + (size_t)(row0 + 8) * ldc + col) = __halves2half2(h2, h3);
                *reinterpret_cast<__half2*>(Cl + cOff + (size_t)row0 * ldc + col) = __halves2half2(l0, l1);
                *reinterpret_cast<__half2*>(Cl + cOff + (size_t)(row0 + 8) * ldc + col) = __halves2half2(l2, l3);
                v0s[nt] = v0; v1s[nt] = v1; v2s[nt] = v2; v3s[nt] = v3;
            } else {
                const __half2 r01 = __floats2half2_rn(v0, v1);
                const __half2 r23 = __floats2half2_rn(v2, v3);
                *reinterpret_cast<__half2*>(Ch + cOff + (size_t)row0 * ldc + col) = r01;
                *reinterpret_cast<__half2*>(Ch + cOff + (size_t)(row0 + 8) * ldc + col) = r23;
                if constexpr (STATS) {
                    // stats from ROUNDED values so PV's exponentials match the sum
                    const float2 f01 = __half22float2(r01);
                    const float2 f23 = __half22float2(r23);
                    v0s[nt] = f01.x; v1s[nt] = f01.y; v2s[nt] = f23.x; v3s[nt] = f23.y;
                }
            }
        }
        if constexpr (STATS) {
            float m0 = -1e30f, m1 = -1e30f;
#pragma unroll
            for (int nt = 0; nt < 4; nt++) {
                m0 = fmaxf(m0, fmaxf(v0s[nt], v1s[nt]));
                m1 = fmaxf(m1, fmaxf(v2s[nt], v3s[nt]));
            }
            float s0 = 0.0f, s1 = 0.0f;
#pragma unroll
            for (int nt = 0; nt < 4; nt++) {
                s0 += __expf(v0s[nt] - m0) + __expf(v1s[nt] - m0);
                s1 += __expf(v2s[nt] - m1) + __expf(v3s[nt] - m1);
            }
#pragma unroll
            for (int o = 1; o <= 2; o <<= 1) {
                float om = __shfl_xor_sync(0xffffffffu, m0, o);
                float os = __shfl_xor_sync(0xffffffffu, s0, o);
                float nm = fmaxf(m0, om);
                s0 = s0 * __expf(m0 - nm) + os * __expf(om - nm);
                m0 = nm;
                om = __shfl_xor_sync(0xffffffffu, m1, o);
                os = __shfl_xor_sync(0xffffffffu, s1, o);
                nm = fmaxf(m1, om);
                s1 = s1 * __expf(m1 - nm) + os * __expf(om - nm);
                m1 = nm;
            }
            if (tq == 0) {
                const int rl = warp_m * 64 + mt * 16 + g;
                srm[rl][warp_n] = m0; srs[rl][warp_n] = s0;
                srm[rl + 8][warp_n] = m1; srs[rl + 8][warp_n] = s1;
            }
        }
    }
    if constexpr (STATS) {
        __syncthreads();
        if (tid < 128) {
            float m = srm[tid][0], s = srs[tid][0];
#pragma unroll
            for (int w = 1; w < 4; w++) {
                const float om = srm[tid][w], os = srs[tid][w];
                const float nm = fmaxf(m, om);
                s = s * __expf(m - nm) + os * __expf(om - nm);
                m = nm;
            }
            const size_t idx = ((size_t)blockIdx.z * SEQ + bm + tid) * NBX + blockIdx.x;
            pm[idx] = m; ps[idx] = s;
        }
    }
}

// ---------------------------------------------------------------------------
// Combine per-CTA partials (NBX=32 per row) into final (max, 1/sum)
// ---------------------------------------------------------------------------
__global__ void __launch_bounds__(256) combine_stats(const float* __restrict__ pm,
                                                     const float* __restrict__ ps,
                                                     float* __restrict__ stats)
{
    const int row = blockIdx.x * 8 + (threadIdx.x >> 5);
    const int lane = threadIdx.x & 31;
    float m = pm[(size_t)row * NBX + lane];
    float s = ps[(size_t)row * NBX + lane];
#pragma unroll
    for (int o = 16; o; o >>= 1) {
        const float om = __shfl_xor_sync(0xffffffffu, m, o);
        const float os = __shfl_xor_sync(0xffffffffu, s, o);
        const float nm = fmaxf(m, om);
        s = s * __expf(m - nm) + os * __expf(om - nm);
        m = nm;
    }
    if (lane == 0) {
        stats[row] = m;
        stats[NROWS + row] = 1.0f / s;
    }
}

// ---------------------------------------------------------------------------
// Fused softmax-normalize + PV GEMM. Reads fp16 RAW scores, writes normalized
// fp32 attn (mandatory output) + runs 1-term PV on fp16 P.
// ---------------------------------------------------------------------------
#define PV_TILE (128 * LDT_B)
#define PV_SMEM (4 * PV_TILE)

__global__ void __launch_bounds__(256) pv_fused(
    const __half* __restrict__ sh, float* __restrict__ attn,
    const float* __restrict__ stats, const __half* __restrict__ vth,
    __half* __restrict__ yh, __half* __restrict__ yl)
{
    extern __shared__ char sm[];
    const uint32_t smb = s2u(sm);
    __shared__ float sm_m[128], sm_inv[128];

    const int tid = threadIdx.x;
    const int wid = tid >> 5, lane = tid & 31;
    const int warp_m = wid & 1, warp_n = wid >> 1;
    const int z = blockIdx.z;
    const int bm = blockIdx.y * 128;

    const __half* shb = sh + (size_t)z * SEQ * SEQ + (size_t)bm * SEQ;
    float* ab = attn + (size_t)z * SEQ * SEQ + (size_t)bm * SEQ;
    const __half* vhb = vth + (size_t)(z * DK) * SEQ;

    const int grow = z * SEQ + bm;
    if (tid < 128) {
        sm_m[tid] = stats[grow + tid];
        sm_inv[tid] = stats[NROWS + grow + tid];
    }
    __syncthreads();

    uint4 pre[2];
    auto ldA = [&](int kb) {
#pragma unroll
        for (int i = 0; i < 2; i++) {
            const int idx = tid + i * 256;
            pre[i] = *reinterpret_cast<const uint4*>(
                shb + (size_t)(idx >> 2) * SEQ + kb + (idx & 3) * 8);
        }
    };
    auto expsts = [&](int kb, int st) {
        const uint32_t as = smb + st * PV_TILE;
#pragma unroll
        for (int i = 0; i < 2; i++) {
            const int idx = tid + i * 256;
            const int r = idx >> 2, sg = idx & 3;
            const float m = sm_m[r], inv = sm_inv[r];
            const __half2* hp = reinterpret_cast<const __half2*>(&pre[i]);
            float p[8];
#pragma unroll
            for (int j = 0; j < 4; j++) {
                const float2 f = __half22float2(hp[j]);
                p[j * 2]     = __expf(f.x - m) * inv;
                p[j * 2 + 1] = __expf(f.y - m) * inv;
            }
            float* ap = ab + (size_t)r * SEQ + kb + sg * 8;
            *reinterpret_cast<float4*>(ap)     = make_float4(p[0], p[1], p[2], p[3]);
            *reinterpret_cast<float4*>(ap + 4) = make_float4(p[4], p[5], p[6], p[7]);
            __half2 h0 = __floats2half2_rn(p[0], p[1]);
            __half2 h1 = __floats2half2_rn(p[2], p[3]);
            __half2 h2 = __floats2half2_rn(p[4], p[5]);
            __half2 h3 = __floats2half2_rn(p[6], p[7]);
            asm volatile("st.shared.v4.b32 [%0], {%1, %2, %3, %4};"
                         :: "r"(as + (uint32_t)(r * LDT_B + sg * 16)),
                            "r"(*reinterpret_cast<uint32_t*>(&h0)),
                            "r"(*reinterpret_cast<uint32_t*>(&h1)),
                            "r"(*reinterpret_cast<uint32_t*>(&h2)),
                            "r"(*reinterpret_cast<uint32_t*>(&h3)));
        }
    };
    auto ldV = [&](int kb, int st) {
        const uint32_t vs = smb + 2 * PV_TILE + st * PV_TILE;
#pragma unroll
        for (int i = 0; i < 2; i++) {
            const int idx = tid + i * 256;
            const int r = idx >> 2, sg = idx & 3;
            cpa16(vs + (uint32_t)(r * LDT_B + sg * 16),
                  vhb + (size_t)r * SEQ + kb + sg * 8);
        }
        cpcommit();
    };

    const uint32_t aoff = (uint32_t)(((lane & 7) + ((lane >> 3) & 1) * 8) * LDT_B + (lane >> 4) * 16);
    const uint32_t boff = (uint32_t)(((lane >> 4) * 8 + (lane & 7)) * LDT_B + ((lane >> 3) & 1) * 16);

    float acc[4][4][4];
#pragma unroll
    for (int i = 0; i < 4; i++)
#pragma unroll
        for (int j = 0; j < 4; j++)
#pragma unroll
            for (int q = 0; q < 4; q++) acc[i][j][q] = 0.0f;

    ldA(0); ldV(0, 0);
    expsts(0, 0);

    const int nch = SEQ / 32;
    for (int c = 0; c < nch; c++) {
        if (c + 1 < nch) { ldA((c + 1) * 32); ldV((c + 1) * 32, (c + 1) & 1); cpwait<1>(); }
        else             { cpwait<0>(); }
        __syncthreads();

        const uint32_t as  = smb + (c & 1) * PV_TILE;
        const uint32_t vhs = smb + 2 * PV_TILE + (c & 1) * PV_TILE;

#pragma unroll
        for (int ks = 0; ks < 2; ks++) {
            const uint32_t kb2 = ks * 32;
            uint32_t A[4][4], B[4][2];
#pragma unroll
            for (int mt = 0; mt < 4; mt++)
                ldm4(A[mt][0], A[mt][1], A[mt][2], A[mt][3],
                     as + (uint32_t)((warp_m * 64 + mt * 16) * LDT_B) + aoff + kb2);
#pragma unroll
            for (int p = 0; p < 2; p++) {
                uint32_t r0, r1, r2, r3;
                ldm4(r0, r1, r2, r3, vhs + (uint32_t)((warp_n * 32 + p * 16) * LDT_B) + boff + kb2);
                B[p * 2][0] = r0; B[p * 2][1] = r1;
                B[p * 2 + 1][0] = r2; B[p * 2 + 1][1] = r3;
            }
#pragma unroll
            for (int mt = 0; mt < 4; mt++)
#pragma unroll
                for (int nt = 0; nt < 4; nt++)
                    mma16816(acc[mt][nt], A[mt], B[nt]);
        }
        if (c + 1 < nch) expsts((c + 1) * 32, (c + 1) & 1);
        __syncthreads();
    }

    const int g = lane >> 2, tq = lane & 3;
#pragma unroll
    for (int mt = 0; mt < 4; mt++) {
        const int row0 = bm + warp_m * 64 + mt * 16 + g;
#pragma unroll
        for (int nt = 0; nt < 4; nt++) {
            const int col = z * DK + warp_n * 32 + nt * 8 + tq * 2;
            const float v0 = acc[mt][nt][0], v1 = acc[mt][nt][1];
            const float v2 = acc[mt][nt][2], v3 = acc[mt][nt][3];
            const __half h0 = __float2half_rn(v0), h1 = __float2half_rn(v1);
            const __half h2 = __float2half_rn(v2), h3 = __float2half_rn(v3);
            const __half l0 = __float2half_rn(v0 - __half2float(h0));
            const __half l1 = __float2half_rn(v1 - __half2float(h1));
            const __half l2 = __float2half_rn(v2 - __half2float(h2));
            const __half l3 = __float2half_rn(v3 - __half2float(h3));
            *reinterpret_cast<__half2*>(yh + (size_t)row0 * HID + col) = __halves2half2(h0, h1);
            *reinterpret_cast<__half2*>(yh + (size_t)(row0 + 8) * HID + col) = __halves2half2(h2, h3);
            *reinterpret_cast<__half2*>(yl + (size_t)row0 * HID + col) = __halves2half2(l0, l1);
            *reinterpret_cast<__half2*>(yl + (size_t)(row0 + 8) * HID + col) = __halves2half2(l2, l3);
        }
    }
}

// ---------------------------------------------------------------------------
// Prep kernels
// ---------------------------------------------------------------------------
__global__ void convert_h(const float* __restrict__ in, __half* __restrict__ oh, int n4)
{
    const int i = blockIdx.x * blockDim.x + threadIdx.x;
    if (i >= n4) return;
    const float4 v = reinterpret_cast<const float4*>(in)[i];
    __half2 ha = __floats2half2_rn(v.x, v.y), hb = __floats2half2_rn(v.z, v.w);
    uint2 uh;
    uh.x = *reinterpret_cast<uint32_t*>(&ha); uh.y = *reinterpret_cast<uint32_t*>(&hb);
    reinterpret_cast<uint2*>(oh)[i] = uh;
}

// transpose fp32 [R][C] -> fp16 hi(/lo) [C][R]
template <int SPLIT>
__global__ void transpose_h(const float* __restrict__ in,
                            __half* __restrict__ oh, __half* __restrict__ ol, int R, int C)
{
    __shared__ float t[32][33];
    const int bc = blockIdx.x * 32, br = blockIdx.y * 32;
    const int x = threadIdx.x, y = threadIdx.y;
#pragma unroll
    for (int j = 0; j < 32; j += 8)
        t[y + j][x] = in[(size_t)(br + y + j) * C + bc + x];
    __syncthreads();
#pragma unroll
    for (int j = 0; j < 32; j += 8) {
        const float v = t[x][y + j];
        const __half h = __float2half_rn(v);
        const size_t o = (size_t)(bc + y + j) * R + br + x;
        oh[o] = h;
        if constexpr (SPLIT) ol[o] = __float2half_rn(v - __half2float(h));
    }
}

// transpose fp16 [R][C] -> fp16 [C][R]
__global__ void transpose_hh(const __half* __restrict__ in, __half* __restrict__ out,
                             int R, int C)
{
    __shared__ __half t[32][34];
    const int bc = blockIdx.x * 32, br = blockIdx.y * 32;
    const int x = threadIdx.x, y = threadIdx.y;
#pragma unroll
    for (int j = 0; j < 32; j += 8)
        t[y + j][x] = in[(size_t)(br + y + j) * C + bc + x];
    __syncthreads();
#pragma unroll
    for (int j = 0; j < 32; j += 8)
        out[(size_t)(bc + y + j) * R + br + x] = t[x][y + j];
}

// ---------------------------------------------------------------------------
extern "C" void kernel_launch(void* const* d_in, const int* in_sizes, int n_in,
                              void* d_out, int out_size)
{
    const float* x  = (const float*)d_in[0];
    const float* Wq = (const float*)d_in[1];
    const float* Wk = (const float*)d_in[2];
    const float* Wv = (const float*)d_in[3];
    const float* Wo = (const float*)d_in[4];
    float* out = (float*)d_out;

    cudaFuncSetAttribute(gemm_mma<2, 1, 0>, cudaFuncAttributeMaxDynamicSharedMemorySize, SMEMSZ);
    cudaFuncSetAttribute(gemm_mma<2, 1, 1>, cudaFuncAttributeMaxDynamicSharedMemorySize, SMEMSZ);
    cudaFuncSetAttribute(gemm_mma<0, 2, 0>, cudaFuncAttributeMaxDynamicSharedMemorySize, SMEMSZ);
    cudaFuncSetAttribute(pv_fused, cudaFuncAttributeMaxDynamicSharedMemorySize, PV_SMEM);

    __half *xh, *wt, *woth, *wotl, *qkv, *vth, *sh, *yh, *yl;
    float *stats, *pm, *ps;
    cudaGetSymbolAddress((void**)&xh, g_xh);
    cudaGetSymbolAddress((void**)&wt, g_wt);
    cudaGetSymbolAddress((void**)&woth, g_woth); cudaGetSymbolAddress((void**)&wotl, g_wotl);
    cudaGetSymbolAddress((void**)&qkv, g_qkv);
    cudaGetSymbolAddress((void**)&vth, g_vth);
    cudaGetSymbolAddress((void**)&sh, g_sh);
    cudaGetSymbolAddress((void**)&yh, g_yh);     cudaGetSymbolAddress((void**)&yl, g_yl);
    cudaGetSymbolAddress((void**)&stats, g_stats);
    cudaGetSymbolAddress((void**)&pm, g_pm);     cudaGetSymbolAddress((void**)&ps, g_ps);

    const size_t ySz = (size_t)SEQ * FEAT;
    const size_t aSz = (size_t)NH * SEQ * SEQ;
    float* attn;
    if ((size_t)out_size >= ySz + aSz) attn = out + ySz;
    else cudaGetSymbolAddress((void**)&attn, g_attn_fb);

    // Prep: x -> fp16; weights -> transposed fp16 (Wo split hi/lo)
    convert_h<<<(SEQ * FEAT / 4 + 255) / 256, 256>>>(x, xh, SEQ * FEAT / 4);
    dim3 tb(32, 8);
    transpose_h<0><<<dim3(HID / 32, FEAT / 32), tb>>>(Wq, wt,                        nullptr, FEAT, HID);
    transpose_h<0><<<dim3(HID / 32, FEAT / 32), tb>>>(Wk, wt + (size_t)HID * FEAT,   nullptr, FEAT, HID);
    transpose_h<0><<<dim3(HID / 32, FEAT / 32), tb>>>(Wv, wt + (size_t)2 * HID * FEAT, nullptr, FEAT, HID);
    transpose_h<1><<<dim3(FEAT / 32, HID / 32), tb>>>(Wo, woth, wotl, HID, FEAT);

    // Fused Q/K/V projection: one launch, z selects weight & output
    gemm_mma<2, 1, 0><<<dim3(HID / 128, SEQ / 128, 3), 256, SMEMSZ>>>(
        xh, nullptr, wt, nullptr, nullptr, qkv, nullptr, nullptr, nullptr,
        FEAT, FEAT, FEAT, HID, 1.0f, 0, (size_t)HID * FEAT, (size_t)SEQ * HID);

    // V^T for PV
    transpose_hh<<<dim3(HID / 32, SEQ / 32), tb>>>(qkv + (size_t)2 * SEQ * HID, vth, SEQ, HID);

    // Scores: 1-term fp16 raw scores + fused softmax partials (from rounded)
    const float alpha = 0.08838834764831845f; // 1/sqrt(128)
    gemm_mma<2, 1, 1><<<dim3(SEQ / 128, SEQ / 128, NH), 256, SMEMSZ>>>(
        qkv, nullptr, qkv + (size_t)SEQ * HID, nullptr, nullptr, sh, nullptr, pm, ps,
        DK, HID, HID, SEQ, alpha,
        (size_t)DK, (size_t)DK, (size_t)SEQ * SEQ);

    // Combine partials into final (max, 1/sum)
    combine_stats<<<NROWS / 8, 256>>>(pm, ps, stats);

    // Fused normalize (fp16 raw -> fp32 attn) + PV (1-term)
    pv_fused<<<dim3(1, SEQ / 128, NH), 256, PV_SMEM>>>(sh, attn, stats, vth, yh, yl);

    // Output projection: 2-term (Y hi/lo x Wo fp16)
    gemm_mma<0, 2, 0><<<dim3(FEAT / 128, SEQ / 128, 1), 256, SMEMSZ>>>(
        yh, yl, woth, wotl, out, nullptr, nullptr, nullptr, nullptr,
        HID, HID, HID, FEAT, 1.0f, 0, 0, 0);
}